// round 2
// baseline (speedup 1.0000x reference)
#include <cuda_runtime.h>
#include <math.h>

#define S_LEN  4096
#define DMODEL 768
#define NH     12
#define DK     64

// Device scratch (allocation-free requirement): projected Q/K/V head-major and
// the concatenated attention output.
__device__ float g_Q[NH * S_LEN * DK];
__device__ float g_K[NH * S_LEN * DK];
__device__ float g_V[NH * S_LEN * DK];
__device__ float g_A[S_LEN * DMODEL];

// ---------------------------------------------------------------------------
// GEMM: Y[m,n] = sum_k X[m,k] * W[n,k] + bias[n]
//   X: [M=4096, K=768] row-major, W: [N=768, K=768] row-major ([out,in])
//   head_major=1 -> Y stored as [n/64][m][n%64]  (for attention input)
//   head_major=0 -> Y stored as [m][n]           (final output)
// 64x64 tile, BK=16, 256 threads, 4x4 register blocking.
// ---------------------------------------------------------------------------
__global__ __launch_bounds__(256) void proj_kernel(
    const float* __restrict__ X, const float* __restrict__ W,
    const float* __restrict__ bias, float* __restrict__ Y, int head_major)
{
    __shared__ float As[16][64 + 4];  // [k][m]
    __shared__ float Bs[16][64 + 4];  // [k][n]

    const int m0  = blockIdx.y * 64;
    const int n0  = blockIdx.x * 64;
    const int tid = threadIdx.x;
    const int ty  = tid >> 4;         // 0..15
    const int tx  = tid & 15;         // 0..15
    const int lr  = tid >> 2;         // 0..63 : row for cooperative loads
    const int lk  = (tid & 3) * 4;    // 0,4,8,12 : k-offset (float4)

    float c[4][4] = {};

    for (int k0 = 0; k0 < DMODEL; k0 += 16) {
        float4 xa = *(const float4*)(X + (size_t)(m0 + lr) * DMODEL + k0 + lk);
        float4 wb = *(const float4*)(W + (size_t)(n0 + lr) * DMODEL + k0 + lk);
        As[lk + 0][lr] = xa.x; As[lk + 1][lr] = xa.y;
        As[lk + 2][lr] = xa.z; As[lk + 3][lr] = xa.w;
        Bs[lk + 0][lr] = wb.x; Bs[lk + 1][lr] = wb.y;
        Bs[lk + 2][lr] = wb.z; Bs[lk + 3][lr] = wb.w;
        __syncthreads();

        #pragma unroll
        for (int kk = 0; kk < 16; kk++) {
            float a[4], b[4];
            #pragma unroll
            for (int i = 0; i < 4; i++) a[i] = As[kk][ty * 4 + i];
            #pragma unroll
            for (int j = 0; j < 4; j++) b[j] = Bs[kk][tx * 4 + j];
            #pragma unroll
            for (int i = 0; i < 4; i++)
                #pragma unroll
                for (int j = 0; j < 4; j++)
                    c[i][j] = fmaf(a[i], b[j], c[i][j]);
        }
        __syncthreads();
    }

    #pragma unroll
    for (int i = 0; i < 4; i++) {
        const int m = m0 + ty * 4 + i;
        #pragma unroll
        for (int j = 0; j < 4; j++) {
            const int n = n0 + tx * 4 + j;
            const float v = c[i][j] + bias[n];
            if (head_major)
                Y[(size_t)(n >> 6) * (S_LEN * DK) + (size_t)m * DK + (n & 63)] = v;
            else
                Y[(size_t)m * DMODEL + n] = v;
        }
    }
}

// ---------------------------------------------------------------------------
// Flash attention, fp32. One block per (head, 64-query tile).
// 256 threads, 4x4 register blocking for both 64x64x64 GEMM phases.
// Smem: exactly 48KB static. K-tile buffer is reused for P (K dead after S).
//
// Tile loads: each 64x64 tile = 64 rows x 16 float4. 256 threads ->
// 4 threads per row (tid&3), each loading 4 float4s (col = ld + c*16).
// ---------------------------------------------------------------------------
__global__ __launch_bounds__(256) void attn_kernel(float* __restrict__ A)
{
    __shared__ float Qt [64][64];  // [d][r]  (Q transposed, pre-scaled)
    __shared__ float KPs[64][64];  // phase 1: Kt[d][c]; phase 2: Ps[r][c]
    __shared__ float Vs [64][64];  // [c][d]

    const int h   = blockIdx.y;
    const int q0  = blockIdx.x * 64;
    const int tid = threadIdx.x;
    const int ty  = tid >> 4;        // 0..15 -> owns rows ty*4..ty*4+3
    const int tx  = tid & 15;        // 0..15 -> owns cols tx*4..tx*4+3
    const int lr  = tid >> 2;        // 0..63
    const int ld  = (tid & 3) * 4;   // 0,4,8,12

    const float* Qg = g_Q + (size_t)h * S_LEN * DK;
    const float* Kg = g_K + (size_t)h * S_LEN * DK;
    const float* Vg = g_V + (size_t)h * S_LEN * DK;

    // Load Q tile transposed, fold in softmax scale 1/sqrt(64).
    #pragma unroll
    for (int cch = 0; cch < 4; cch++) {
        const int col = ld + cch * 16;     // covers 0..60 step 4 over (tid&3, cch)
        float4 qv = *(const float4*)(Qg + (size_t)(q0 + lr) * DK + col);
        const float sc = 0.125f;
        Qt[col + 0][lr] = qv.x * sc; Qt[col + 1][lr] = qv.y * sc;
        Qt[col + 2][lr] = qv.z * sc; Qt[col + 3][lr] = qv.w * sc;
    }

    float acc[4][4] = {};
    float m_run[4], l_run[4];
    #pragma unroll
    for (int i = 0; i < 4; i++) { m_run[i] = -INFINITY; l_run[i] = 0.f; }
    __syncthreads();

    for (int kv0 = 0; kv0 < S_LEN; kv0 += 64) {
        // Load K (transposed) and V (direct) tiles -- full 64x64 coverage.
        #pragma unroll
        for (int cch = 0; cch < 4; cch++) {
            const int col = ld + cch * 16;
            float4 kvv = *(const float4*)(Kg + (size_t)(kv0 + lr) * DK + col);
            KPs[col + 0][lr] = kvv.x; KPs[col + 1][lr] = kvv.y;
            KPs[col + 2][lr] = kvv.z; KPs[col + 3][lr] = kvv.w;
            float4 vv = *(const float4*)(Vg + (size_t)(kv0 + lr) * DK + col);
            *(float4*)(&Vs[lr][col]) = vv;
        }
        __syncthreads();

        // S = (Q * scale) K^T  -- outer product over d.
        float s[4][4] = {};
        #pragma unroll 8
        for (int d = 0; d < 64; d++) {
            float a[4], b[4];
            #pragma unroll
            for (int i = 0; i < 4; i++) a[i] = Qt[d][ty * 4 + i];
            #pragma unroll
            for (int j = 0; j < 4; j++) b[j] = KPs[d][tx * 4 + j];
            #pragma unroll
            for (int i = 0; i < 4; i++)
                #pragma unroll
                for (int j = 0; j < 4; j++)
                    s[i][j] = fmaf(a[i], b[j], s[i][j]);
        }

        // Online softmax update (row reductions across the 16 tx-threads,
        // which sit in aligned width-16 shuffle segments).
        #pragma unroll
        for (int i = 0; i < 4; i++) {
            float tm = fmaxf(fmaxf(s[i][0], s[i][1]), fmaxf(s[i][2], s[i][3]));
            #pragma unroll
            for (int o = 1; o < 16; o <<= 1)
                tm = fmaxf(tm, __shfl_xor_sync(0xffffffffu, tm, o, 16));
            const float mn   = fmaxf(m_run[i], tm);
            const float corr = __expf(m_run[i] - mn);
            m_run[i] = mn;
            float rs = 0.f;
            #pragma unroll
            for (int j = 0; j < 4; j++) {
                s[i][j] = __expf(s[i][j] - mn);
                rs += s[i][j];
            }
            #pragma unroll
            for (int o = 1; o < 16; o <<= 1)
                rs += __shfl_xor_sync(0xffffffffu, rs, o, 16);
            l_run[i] = l_run[i] * corr + rs;
            #pragma unroll
            for (int j = 0; j < 4; j++) acc[i][j] *= corr;
        }
        __syncthreads();  // everyone done reading KPs as K

        // Store P into the (now dead) K buffer: Ps[r][c], conflict-free STS.128.
        #pragma unroll
        for (int i = 0; i < 4; i++)
            *(float4*)(&KPs[ty * 4 + i][tx * 4]) =
                make_float4(s[i][0], s[i][1], s[i][2], s[i][3]);
        __syncthreads();

        // O += P V -- outer product over c. Column-of-P loads are warp
        // broadcasts (c is uniform), V loads are conflict-free LDS.128.
        #pragma unroll 8
        for (int c = 0; c < 64; c++) {
            float a[4];
            #pragma unroll
            for (int i = 0; i < 4; i++) a[i] = KPs[ty * 4 + i][c];
            const float4 bv = *(const float4*)(&Vs[c][tx * 4]);
            const float b[4] = { bv.x, bv.y, bv.z, bv.w };
            #pragma unroll
            for (int i = 0; i < 4; i++)
                #pragma unroll
                for (int j = 0; j < 4; j++)
                    acc[i][j] = fmaf(a[i], b[j], acc[i][j]);
        }
        __syncthreads();  // before next tile overwrites KPs / Vs
    }

    // Normalize and write concat layout: A[s][h*64 + d].
    #pragma unroll
    for (int i = 0; i < 4; i++) {
        const float inv = 1.f / l_run[i];
        const int r = q0 + ty * 4 + i;
        float4 o = make_float4(acc[i][0] * inv, acc[i][1] * inv,
                               acc[i][2] * inv, acc[i][3] * inv);
        *(float4*)(&A[(size_t)r * DMODEL + h * DK + tx * 4]) = o;
    }
}

// ---------------------------------------------------------------------------
extern "C" void kernel_launch(void* const* d_in, const int* in_sizes, int n_in,
                              void* d_out, int out_size)
{
    const float* q  = (const float*)d_in[0];
    const float* k  = (const float*)d_in[1];
    const float* v  = (const float*)d_in[2];
    const float* Wq = (const float*)d_in[3];
    const float* bq = (const float*)d_in[4];
    const float* Wo = (const float*)d_in[5];
    const float* bo = (const float*)d_in[6];
    float* out = (float*)d_out;

    float *gQ, *gK, *gV, *gA;
    cudaGetSymbolAddress((void**)&gQ, g_Q);
    cudaGetSymbolAddress((void**)&gK, g_K);
    cudaGetSymbolAddress((void**)&gV, g_V);
    cudaGetSymbolAddress((void**)&gA, g_A);

    dim3 gproj(DMODEL / 64, S_LEN / 64);  // 12 x 64
    proj_kernel<<<gproj, 256>>>(q, Wq, bq, gQ, 1);
    proj_kernel<<<gproj, 256>>>(k, Wq, bq, gK, 1);
    proj_kernel<<<gproj, 256>>>(v, Wq, bq, gV, 1);

    dim3 gattn(S_LEN / 64, NH);           // 64 x 12
    attn_kernel<<<gattn, 256>>>(gA);

    proj_kernel<<<gproj, 256>>>(gA, Wo, bo, out, 0);
}

// round 3
// speedup vs baseline: 1.0017x; 1.0017x over previous
#include <cuda_runtime.h>
#include <math.h>

#define S_LEN  4096
#define DMODEL 768
#define NH     12
#define DK     64

// Device scratch (allocation-free requirement): projected Q/K/V head-major and
// the concatenated attention output.
__device__ float g_Q[NH * S_LEN * DK];
__device__ float g_K[NH * S_LEN * DK];
__device__ float g_V[NH * S_LEN * DK];
__device__ float g_A[S_LEN * DMODEL];

// ---------------------------------------------------------------------------
// GEMM: Y[m,n] = sum_k X[m,k] * W[n,k] + bias[n]
//   X: [M=4096, K=768] row-major, W: [N=768, K=768] row-major ([out,in])
//   head_major=1 -> Y stored as [n/64][m][n%64]  (for attention input)
//   head_major=0 -> Y stored as [m][n]           (final output)
// 64x64 tile, BK=16, 256 threads, 4x4 register blocking.
// ---------------------------------------------------------------------------
__global__ __launch_bounds__(256) void proj_kernel(
    const float* __restrict__ X, const float* __restrict__ W,
    const float* __restrict__ bias, float* __restrict__ Y, int head_major)
{
    __shared__ float As[16][64 + 4];  // [k][m]
    __shared__ float Bs[16][64 + 4];  // [k][n]

    const int m0  = blockIdx.y * 64;
    const int n0  = blockIdx.x * 64;
    const int tid = threadIdx.x;
    const int ty  = tid >> 4;         // 0..15
    const int tx  = tid & 15;         // 0..15
    const int lr  = tid >> 2;         // 0..63 : row for cooperative loads
    const int lk  = (tid & 3) * 4;    // 0,4,8,12 : k-offset (float4)

    float c[4][4] = {};

    for (int k0 = 0; k0 < DMODEL; k0 += 16) {
        float4 xa = *(const float4*)(X + (size_t)(m0 + lr) * DMODEL + k0 + lk);
        float4 wb = *(const float4*)(W + (size_t)(n0 + lr) * DMODEL + k0 + lk);
        As[lk + 0][lr] = xa.x; As[lk + 1][lr] = xa.y;
        As[lk + 2][lr] = xa.z; As[lk + 3][lr] = xa.w;
        Bs[lk + 0][lr] = wb.x; Bs[lk + 1][lr] = wb.y;
        Bs[lk + 2][lr] = wb.z; Bs[lk + 3][lr] = wb.w;
        __syncthreads();

        #pragma unroll
        for (int kk = 0; kk < 16; kk++) {
            float a[4], b[4];
            #pragma unroll
            for (int i = 0; i < 4; i++) a[i] = As[kk][ty * 4 + i];
            #pragma unroll
            for (int j = 0; j < 4; j++) b[j] = Bs[kk][tx * 4 + j];
            #pragma unroll
            for (int i = 0; i < 4; i++)
                #pragma unroll
                for (int j = 0; j < 4; j++)
                    c[i][j] = fmaf(a[i], b[j], c[i][j]);
        }
        __syncthreads();
    }

    #pragma unroll
    for (int i = 0; i < 4; i++) {
        const int m = m0 + ty * 4 + i;
        #pragma unroll
        for (int j = 0; j < 4; j++) {
            const int n = n0 + tx * 4 + j;
            const float v = c[i][j] + bias[n];
            if (head_major)
                Y[(size_t)(n >> 6) * (S_LEN * DK) + (size_t)m * DK + (n & 63)] = v;
            else
                Y[(size_t)m * DMODEL + n] = v;
        }
    }
}

// ---------------------------------------------------------------------------
// Flash attention, fp32. One block per (head, 64-query tile).
// 256 threads, 4x4 register blocking for both 64x64x64 GEMM phases.
// Smem: exactly 48KB static. K-tile buffer is reused for P (K dead after S).
//
// Tile loads: each 64x64 tile = 64 rows x 16 float4. 256 threads ->
// 4 threads per row (tid&3), each loading 4 float4s (col = ld + c*16).
// ---------------------------------------------------------------------------
__global__ __launch_bounds__(256) void attn_kernel(float* __restrict__ A)
{
    __shared__ float Qt [64][64];  // [d][r]  (Q transposed, pre-scaled)
    __shared__ float KPs[64][64];  // phase 1: Kt[d][c]; phase 2: Ps[r][c]
    __shared__ float Vs [64][64];  // [c][d]

    const int h   = blockIdx.y;
    const int q0  = blockIdx.x * 64;
    const int tid = threadIdx.x;
    const int ty  = tid >> 4;        // 0..15 -> owns rows ty*4..ty*4+3
    const int tx  = tid & 15;        // 0..15 -> owns cols tx*4..tx*4+3
    const int lr  = tid >> 2;        // 0..63
    const int ld  = (tid & 3) * 4;   // 0,4,8,12

    const float* Qg = g_Q + (size_t)h * S_LEN * DK;
    const float* Kg = g_K + (size_t)h * S_LEN * DK;
    const float* Vg = g_V + (size_t)h * S_LEN * DK;

    // Load Q tile transposed, fold in softmax scale 1/sqrt(64).
    #pragma unroll
    for (int cch = 0; cch < 4; cch++) {
        const int col = ld + cch * 16;     // covers 0..60 step 4 over (tid&3, cch)
        float4 qv = *(const float4*)(Qg + (size_t)(q0 + lr) * DK + col);
        const float sc = 0.125f;
        Qt[col + 0][lr] = qv.x * sc; Qt[col + 1][lr] = qv.y * sc;
        Qt[col + 2][lr] = qv.z * sc; Qt[col + 3][lr] = qv.w * sc;
    }

    float acc[4][4] = {};
    float m_run[4], l_run[4];
    #pragma unroll
    for (int i = 0; i < 4; i++) { m_run[i] = -INFINITY; l_run[i] = 0.f; }
    __syncthreads();

    for (int kv0 = 0; kv0 < S_LEN; kv0 += 64) {
        // Load K (transposed) and V (direct) tiles -- full 64x64 coverage.
        #pragma unroll
        for (int cch = 0; cch < 4; cch++) {
            const int col = ld + cch * 16;
            float4 kvv = *(const float4*)(Kg + (size_t)(kv0 + lr) * DK + col);
            KPs[col + 0][lr] = kvv.x; KPs[col + 1][lr] = kvv.y;
            KPs[col + 2][lr] = kvv.z; KPs[col + 3][lr] = kvv.w;
            float4 vv = *(const float4*)(Vg + (size_t)(kv0 + lr) * DK + col);
            *(float4*)(&Vs[lr][col]) = vv;
        }
        __syncthreads();

        // S = (Q * scale) K^T  -- outer product over d.
        float s[4][4] = {};
        #pragma unroll 8
        for (int d = 0; d < 64; d++) {
            float a[4], b[4];
            #pragma unroll
            for (int i = 0; i < 4; i++) a[i] = Qt[d][ty * 4 + i];
            #pragma unroll
            for (int j = 0; j < 4; j++) b[j] = KPs[d][tx * 4 + j];
            #pragma unroll
            for (int i = 0; i < 4; i++)
                #pragma unroll
                for (int j = 0; j < 4; j++)
                    s[i][j] = fmaf(a[i], b[j], s[i][j]);
        }

        // Online softmax update (row reductions across the 16 tx-threads,
        // which sit in aligned width-16 shuffle segments).
        #pragma unroll
        for (int i = 0; i < 4; i++) {
            float tm = fmaxf(fmaxf(s[i][0], s[i][1]), fmaxf(s[i][2], s[i][3]));
            #pragma unroll
            for (int o = 1; o < 16; o <<= 1)
                tm = fmaxf(tm, __shfl_xor_sync(0xffffffffu, tm, o, 16));
            const float mn   = fmaxf(m_run[i], tm);
            const float corr = __expf(m_run[i] - mn);
            m_run[i] = mn;
            float rs = 0.f;
            #pragma unroll
            for (int j = 0; j < 4; j++) {
                s[i][j] = __expf(s[i][j] - mn);
                rs += s[i][j];
            }
            #pragma unroll
            for (int o = 1; o < 16; o <<= 1)
                rs += __shfl_xor_sync(0xffffffffu, rs, o, 16);
            l_run[i] = l_run[i] * corr + rs;
            #pragma unroll
            for (int j = 0; j < 4; j++) acc[i][j] *= corr;
        }
        __syncthreads();  // everyone done reading KPs as K

        // Store P into the (now dead) K buffer: Ps[r][c], conflict-free STS.128.
        #pragma unroll
        for (int i = 0; i < 4; i++)
            *(float4*)(&KPs[ty * 4 + i][tx * 4]) =
                make_float4(s[i][0], s[i][1], s[i][2], s[i][3]);
        __syncthreads();

        // O += P V -- outer product over c. Column-of-P loads are warp
        // broadcasts (c is uniform), V loads are conflict-free LDS.128.
        #pragma unroll 8
        for (int c = 0; c < 64; c++) {
            float a[4];
            #pragma unroll
            for (int i = 0; i < 4; i++) a[i] = KPs[ty * 4 + i][c];
            const float4 bv = *(const float4*)(&Vs[c][tx * 4]);
            const float b[4] = { bv.x, bv.y, bv.z, bv.w };
            #pragma unroll
            for (int i = 0; i < 4; i++)
                #pragma unroll
                for (int j = 0; j < 4; j++)
                    acc[i][j] = fmaf(a[i], b[j], acc[i][j]);
        }
        __syncthreads();  // before next tile overwrites KPs / Vs
    }

    // Normalize and write concat layout: A[s][h*64 + d].
    #pragma unroll
    for (int i = 0; i < 4; i++) {
        const float inv = 1.f / l_run[i];
        const int r = q0 + ty * 4 + i;
        float4 o = make_float4(acc[i][0] * inv, acc[i][1] * inv,
                               acc[i][2] * inv, acc[i][3] * inv);
        *(float4*)(&A[(size_t)r * DMODEL + h * DK + tx * 4]) = o;
    }
}

// ---------------------------------------------------------------------------
extern "C" void kernel_launch(void* const* d_in, const int* in_sizes, int n_in,
                              void* d_out, int out_size)
{
    const float* q  = (const float*)d_in[0];
    const float* k  = (const float*)d_in[1];
    const float* v  = (const float*)d_in[2];
    const float* Wq = (const float*)d_in[3];
    const float* bq = (const float*)d_in[4];
    const float* Wo = (const float*)d_in[5];
    const float* bo = (const float*)d_in[6];
    float* out = (float*)d_out;

    float *gQ, *gK, *gV, *gA;
    cudaGetSymbolAddress((void**)&gQ, g_Q);
    cudaGetSymbolAddress((void**)&gK, g_K);
    cudaGetSymbolAddress((void**)&gV, g_V);
    cudaGetSymbolAddress((void**)&gA, g_A);

    dim3 gproj(DMODEL / 64, S_LEN / 64);  // 12 x 64
    proj_kernel<<<gproj, 256>>>(q, Wq, bq, gQ, 1);
    proj_kernel<<<gproj, 256>>>(k, Wq, bq, gK, 1);
    proj_kernel<<<gproj, 256>>>(v, Wq, bq, gV, 1);

    dim3 gattn(S_LEN / 64, NH);           // 64 x 12
    attn_kernel<<<gattn, 256>>>(gA);

    proj_kernel<<<gproj, 256>>>(gA, Wo, bo, out, 0);
}

// round 4
// speedup vs baseline: 1.0026x; 1.0010x over previous
#include <cuda_runtime.h>
#include <math.h>

#define S_LEN  4096
#define DMODEL 768
#define NH     12
#define DK     64

// Device scratch (allocation-free requirement): projected Q/K/V head-major and
// the concatenated attention output.
__device__ float g_Q[NH * S_LEN * DK];
__device__ float g_K[NH * S_LEN * DK];
__device__ float g_V[NH * S_LEN * DK];
__device__ float g_A[S_LEN * DMODEL];

// ---------------------------------------------------------------------------
// GEMM: Y[m,n] = sum_k X[m,k] * W[n,k] + bias[n]
//   X: [M=4096, K=768] row-major, W: [N=768, K=768] row-major ([out,in])
//   head_major=1 -> Y stored as [n/64][m][n%64]  (for attention input)
//   head_major=0 -> Y stored as [m][n]           (final output)
// 64x64 tile, BK=16, 256 threads, 4x4 register blocking.
// ---------------------------------------------------------------------------
__global__ __launch_bounds__(256) void proj_kernel(
    const float* __restrict__ X, const float* __restrict__ W,
    const float* __restrict__ bias, float* __restrict__ Y, int head_major)
{
    __shared__ float As[16][64 + 4];  // [k][m]
    __shared__ float Bs[16][64 + 4];  // [k][n]

    const int m0  = blockIdx.y * 64;
    const int n0  = blockIdx.x * 64;
    const int tid = threadIdx.x;
    const int ty  = tid >> 4;         // 0..15
    const int tx  = tid & 15;         // 0..15
    const int lr  = tid >> 2;         // 0..63 : row for cooperative loads
    const int lk  = (tid & 3) * 4;    // 0,4,8,12 : k-offset (float4)

    float c[4][4] = {};

    for (int k0 = 0; k0 < DMODEL; k0 += 16) {
        float4 xa = *(const float4*)(X + (size_t)(m0 + lr) * DMODEL + k0 + lk);
        float4 wb = *(const float4*)(W + (size_t)(n0 + lr) * DMODEL + k0 + lk);
        As[lk + 0][lr] = xa.x; As[lk + 1][lr] = xa.y;
        As[lk + 2][lr] = xa.z; As[lk + 3][lr] = xa.w;
        Bs[lk + 0][lr] = wb.x; Bs[lk + 1][lr] = wb.y;
        Bs[lk + 2][lr] = wb.z; Bs[lk + 3][lr] = wb.w;
        __syncthreads();

        #pragma unroll
        for (int kk = 0; kk < 16; kk++) {
            float a[4], b[4];
            #pragma unroll
            for (int i = 0; i < 4; i++) a[i] = As[kk][ty * 4 + i];
            #pragma unroll
            for (int j = 0; j < 4; j++) b[j] = Bs[kk][tx * 4 + j];
            #pragma unroll
            for (int i = 0; i < 4; i++)
                #pragma unroll
                for (int j = 0; j < 4; j++)
                    c[i][j] = fmaf(a[i], b[j], c[i][j]);
        }
        __syncthreads();
    }

    #pragma unroll
    for (int i = 0; i < 4; i++) {
        const int m = m0 + ty * 4 + i;
        #pragma unroll
        for (int j = 0; j < 4; j++) {
            const int n = n0 + tx * 4 + j;
            const float v = c[i][j] + bias[n];
            if (head_major)
                Y[(size_t)(n >> 6) * (S_LEN * DK) + (size_t)m * DK + (n & 63)] = v;
            else
                Y[(size_t)m * DMODEL + n] = v;
        }
    }
}

// ---------------------------------------------------------------------------
// Flash attention, fp32. One block per (head, 64-query tile).
// 256 threads, 4x4 register blocking for both 64x64x64 GEMM phases.
// Smem: exactly 48KB static. K-tile buffer is reused for P (K dead after S).
//
// Tile loads: each 64x64 tile = 64 rows x 16 float4. 256 threads ->
// 4 threads per row (tid&3), each loading 4 float4s (col = ld + c*16).
// ---------------------------------------------------------------------------
__global__ __launch_bounds__(256) void attn_kernel(float* __restrict__ A)
{
    __shared__ float Qt [64][64];  // [d][r]  (Q transposed, pre-scaled)
    __shared__ float KPs[64][64];  // phase 1: Kt[d][c]; phase 2: Ps[r][c]
    __shared__ float Vs [64][64];  // [c][d]

    const int h   = blockIdx.y;
    const int q0  = blockIdx.x * 64;
    const int tid = threadIdx.x;
    const int ty  = tid >> 4;        // 0..15 -> owns rows ty*4..ty*4+3
    const int tx  = tid & 15;        // 0..15 -> owns cols tx*4..tx*4+3
    const int lr  = tid >> 2;        // 0..63
    const int ld  = (tid & 3) * 4;   // 0,4,8,12

    const float* Qg = g_Q + (size_t)h * S_LEN * DK;
    const float* Kg = g_K + (size_t)h * S_LEN * DK;
    const float* Vg = g_V + (size_t)h * S_LEN * DK;

    // Load Q tile transposed, fold in softmax scale 1/sqrt(64).
    #pragma unroll
    for (int cch = 0; cch < 4; cch++) {
        const int col = ld + cch * 16;     // covers 0..60 step 4 over (tid&3, cch)
        float4 qv = *(const float4*)(Qg + (size_t)(q0 + lr) * DK + col);
        const float sc = 0.125f;
        Qt[col + 0][lr] = qv.x * sc; Qt[col + 1][lr] = qv.y * sc;
        Qt[col + 2][lr] = qv.z * sc; Qt[col + 3][lr] = qv.w * sc;
    }

    float acc[4][4] = {};
    float m_run[4], l_run[4];
    #pragma unroll
    for (int i = 0; i < 4; i++) { m_run[i] = -INFINITY; l_run[i] = 0.f; }
    __syncthreads();

    for (int kv0 = 0; kv0 < S_LEN; kv0 += 64) {
        // Load K (transposed) and V (direct) tiles -- full 64x64 coverage.
        #pragma unroll
        for (int cch = 0; cch < 4; cch++) {
            const int col = ld + cch * 16;
            float4 kvv = *(const float4*)(Kg + (size_t)(kv0 + lr) * DK + col);
            KPs[col + 0][lr] = kvv.x; KPs[col + 1][lr] = kvv.y;
            KPs[col + 2][lr] = kvv.z; KPs[col + 3][lr] = kvv.w;
            float4 vv = *(const float4*)(Vg + (size_t)(kv0 + lr) * DK + col);
            *(float4*)(&Vs[lr][col]) = vv;
        }
        __syncthreads();

        // S = (Q * scale) K^T  -- outer product over d.
        float s[4][4] = {};
        #pragma unroll 8
        for (int d = 0; d < 64; d++) {
            float a[4], b[4];
            #pragma unroll
            for (int i = 0; i < 4; i++) a[i] = Qt[d][ty * 4 + i];
            #pragma unroll
            for (int j = 0; j < 4; j++) b[j] = KPs[d][tx * 4 + j];
            #pragma unroll
            for (int i = 0; i < 4; i++)
                #pragma unroll
                for (int j = 0; j < 4; j++)
                    s[i][j] = fmaf(a[i], b[j], s[i][j]);
        }

        // Online softmax update (row reductions across the 16 tx-threads,
        // which sit in aligned width-16 shuffle segments).
        #pragma unroll
        for (int i = 0; i < 4; i++) {
            float tm = fmaxf(fmaxf(s[i][0], s[i][1]), fmaxf(s[i][2], s[i][3]));
            #pragma unroll
            for (int o = 1; o < 16; o <<= 1)
                tm = fmaxf(tm, __shfl_xor_sync(0xffffffffu, tm, o, 16));
            const float mn   = fmaxf(m_run[i], tm);
            const float corr = __expf(m_run[i] - mn);
            m_run[i] = mn;
            float rs = 0.f;
            #pragma unroll
            for (int j = 0; j < 4; j++) {
                s[i][j] = __expf(s[i][j] - mn);
                rs += s[i][j];
            }
            #pragma unroll
            for (int o = 1; o < 16; o <<= 1)
                rs += __shfl_xor_sync(0xffffffffu, rs, o, 16);
            l_run[i] = l_run[i] * corr + rs;
            #pragma unroll
            for (int j = 0; j < 4; j++) acc[i][j] *= corr;
        }
        __syncthreads();  // everyone done reading KPs as K

        // Store P into the (now dead) K buffer: Ps[r][c], conflict-free STS.128.
        #pragma unroll
        for (int i = 0; i < 4; i++)
            *(float4*)(&KPs[ty * 4 + i][tx * 4]) =
                make_float4(s[i][0], s[i][1], s[i][2], s[i][3]);
        __syncthreads();

        // O += P V -- outer product over c. Column-of-P loads are warp
        // broadcasts (c is uniform), V loads are conflict-free LDS.128.
        #pragma unroll 8
        for (int c = 0; c < 64; c++) {
            float a[4];
            #pragma unroll
            for (int i = 0; i < 4; i++) a[i] = KPs[ty * 4 + i][c];
            const float4 bv = *(const float4*)(&Vs[c][tx * 4]);
            const float b[4] = { bv.x, bv.y, bv.z, bv.w };
            #pragma unroll
            for (int i = 0; i < 4; i++)
                #pragma unroll
                for (int j = 0; j < 4; j++)
                    acc[i][j] = fmaf(a[i], b[j], acc[i][j]);
        }
        __syncthreads();  // before next tile overwrites KPs / Vs
    }

    // Normalize and write concat layout: A[s][h*64 + d].
    #pragma unroll
    for (int i = 0; i < 4; i++) {
        const float inv = 1.f / l_run[i];
        const int r = q0 + ty * 4 + i;
        float4 o = make_float4(acc[i][0] * inv, acc[i][1] * inv,
                               acc[i][2] * inv, acc[i][3] * inv);
        *(float4*)(&A[(size_t)r * DMODEL + h * DK + tx * 4]) = o;
    }
}

// ---------------------------------------------------------------------------
extern "C" void kernel_launch(void* const* d_in, const int* in_sizes, int n_in,
                              void* d_out, int out_size)
{
    const float* q  = (const float*)d_in[0];
    const float* k  = (const float*)d_in[1];
    const float* v  = (const float*)d_in[2];
    const float* Wq = (const float*)d_in[3];
    const float* bq = (const float*)d_in[4];
    const float* Wo = (const float*)d_in[5];
    const float* bo = (const float*)d_in[6];
    float* out = (float*)d_out;

    float *gQ, *gK, *gV, *gA;
    cudaGetSymbolAddress((void**)&gQ, g_Q);
    cudaGetSymbolAddress((void**)&gK, g_K);
    cudaGetSymbolAddress((void**)&gV, g_V);
    cudaGetSymbolAddress((void**)&gA, g_A);

    dim3 gproj(DMODEL / 64, S_LEN / 64);  // 12 x 64
    proj_kernel<<<gproj, 256>>>(q, Wq, bq, gQ, 1);
    proj_kernel<<<gproj, 256>>>(k, Wq, bq, gK, 1);
    proj_kernel<<<gproj, 256>>>(v, Wq, bq, gV, 1);

    dim3 gattn(S_LEN / 64, NH);           // 64 x 12
    attn_kernel<<<gattn, 256>>>(gA);

    proj_kernel<<<gproj, 256>>>(gA, Wo, bo, out, 0);
}

// round 6
// speedup vs baseline: 2.5110x; 2.5043x over previous
#include <cuda_runtime.h>
#include <cuda_bf16.h>
#include <math.h>
#include <stdint.h>

#define S_LEN 4096
#define DMODEL 768
#define NH 12
#define DK 64
#define XN (S_LEN * DMODEL)
#define WN (DMODEL * DMODEL)

__device__ __nv_bfloat16 g_xh[3 * XN], g_xl[3 * XN];
__device__ __nv_bfloat16 g_wh[2 * WN], g_wl[2 * WN];
__device__ __nv_bfloat16 g_qh[XN], g_ql[XN], g_kh[XN], g_kl[XN], g_vh[XN], g_vl[XN];
__device__ __nv_bfloat16 g_ah[XN], g_al[XN];

__device__ __forceinline__ uint32_t smem_u32(const void* p) {
    uint32_t a;
    asm("{ .reg .u64 t; cvta.to.shared.u64 t, %1; cvt.u32.u64 %0, t; }" : "=r"(a) : "l"(p));
    return a;
}
__device__ __forceinline__ float ex2f(float x) {
    float r; asm("ex2.approx.ftz.f32 %0, %1;" : "=f"(r) : "f"(x)); return r;
}
__device__ __forceinline__ uint32_t pack_bf16(float a, float b) {  // low=a, high=b
    uint32_t r; asm("cvt.rn.satfinite.bf16x2.f32 %0, %1, %2;" : "=r"(r) : "f"(b), "f"(a)); return r;
}
__device__ __forceinline__ void ldsm4(uint32_t* r, uint32_t a) {
    asm volatile("ldmatrix.sync.aligned.m8n8.x4.shared.b16 {%0,%1,%2,%3}, [%4];"
                 : "=r"(r[0]), "=r"(r[1]), "=r"(r[2]), "=r"(r[3]) : "r"(a));
}
__device__ __forceinline__ void ldsm4t(uint32_t* r, uint32_t a) {
    asm volatile("ldmatrix.sync.aligned.m8n8.x4.trans.shared.b16 {%0,%1,%2,%3}, [%4];"
                 : "=r"(r[0]), "=r"(r[1]), "=r"(r[2]), "=r"(r[3]) : "r"(a));
}
__device__ __forceinline__ void mma16816(float* d, const uint32_t* a, const uint32_t* b) {
    asm volatile("mma.sync.aligned.m16n8k16.row.col.f32.bf16.bf16.f32 "
                 "{%0,%1,%2,%3}, {%4,%5,%6,%7}, {%8,%9}, {%0,%1,%2,%3};"
                 : "+f"(d[0]), "+f"(d[1]), "+f"(d[2]), "+f"(d[3])
                 : "r"(a[0]), "r"(a[1]), "r"(a[2]), "r"(a[3]), "r"(b[0]), "r"(b[1]));
}

__global__ void conv_hilo(const float* __restrict__ in, __nv_bfloat16* __restrict__ hi,
                          __nv_bfloat16* __restrict__ lo, int n4)
{
    int i = blockIdx.x * blockDim.x + threadIdx.x;
    if (i >= n4) return;
    float4 v = ((const float4*)in)[i];
    uint32_t h01 = pack_bf16(v.x, v.y), h23 = pack_bf16(v.z, v.w);
    __nv_bfloat162 a = *(__nv_bfloat162*)&h01, b = *(__nv_bfloat162*)&h23;
    ((uint32_t*)hi)[2 * i] = h01; ((uint32_t*)hi)[2 * i + 1] = h23;
    ((uint32_t*)lo)[2 * i]     = pack_bf16(v.x - __bfloat162float(a.x), v.y - __bfloat162float(a.y));
    ((uint32_t*)lo)[2 * i + 1] = pack_bf16(v.z - __bfloat162float(b.x), v.w - __bfloat162float(b.y));
}

// Y[m,n] = sum_k X[m,k] W[n,k] + bias[n]; 128x128 block, KCH=32, hi/lo 3-pass.
// MODE: 0 = Q *0.125*log2e -> [h][s][64] ; 1 = K/V -> [h][s][64] ; 3 = fp32 [m][n]
template <int MODE>
__global__ void __launch_bounds__(256) proj_tc(
    const __nv_bfloat16* __restrict__ Xh, const __nv_bfloat16* __restrict__ Xl,
    const __nv_bfloat16* __restrict__ Wh, const __nv_bfloat16* __restrict__ Wl,
    const float* __restrict__ bias,
    __nv_bfloat16* __restrict__ Yh, __nv_bfloat16* __restrict__ Yl, float* __restrict__ Yf)
{
    __shared__ __nv_bfloat16 Ahs[128][40], Als[128][40], Bhs[128][40], Bls[128][40];
    const int tid = threadIdx.x, w = tid >> 5, lid = tid & 31;
    const int wm = w >> 1, wn = w & 1;
    const int m0 = blockIdx.y * 128, n0 = blockIdx.x * 128;

    float acc[2][8][4] = {};

    for (int k0 = 0; k0 < DMODEL; k0 += 32) {
        #pragma unroll
        for (int i = 0; i < 2; i++) {
            int idx = tid + i * 256;                   // 512 uint4 per array
            int r = idx >> 2, c8 = (idx & 3) * 8;
            size_t xs = (size_t)(m0 + r) * DMODEL + k0 + c8;
            size_t ws = (size_t)(n0 + r) * DMODEL + k0 + c8;
            *(uint4*)&Ahs[r][c8] = *(const uint4*)(Xh + xs);
            *(uint4*)&Als[r][c8] = *(const uint4*)(Xl + xs);
            *(uint4*)&Bhs[r][c8] = *(const uint4*)(Wh + ws);
            *(uint4*)&Bls[r][c8] = *(const uint4*)(Wl + ws);
        }
        __syncthreads();
        #pragma unroll
        for (int ks = 0; ks < 32; ks += 16) {
            const int ac = ks + ((lid >> 4) << 3);
            uint32_t ah[2][4], al[2][4], bh[8][2], bl[8][2], r4[4];
            #pragma unroll
            for (int jp = 0; jp < 4; jp++) {
                int rB = 64 * wn + 16 * jp + (lid & 15);
                ldsm4(r4, smem_u32(&Bhs[rB][ac]));
                bh[2*jp][0]=r4[0]; bh[2*jp][1]=r4[2]; bh[2*jp+1][0]=r4[1]; bh[2*jp+1][1]=r4[3];
                ldsm4(r4, smem_u32(&Bls[rB][ac]));
                bl[2*jp][0]=r4[0]; bl[2*jp][1]=r4[2]; bl[2*jp+1][0]=r4[1]; bl[2*jp+1][1]=r4[3];
            }
            #pragma unroll
            for (int i = 0; i < 2; i++) {
                int rA = 32 * wm + 16 * i + (lid & 15);
                ldsm4(ah[i], smem_u32(&Ahs[rA][ac]));
                ldsm4(al[i], smem_u32(&Als[rA][ac]));
            }
            #pragma unroll
            for (int i = 0; i < 2; i++)
                #pragma unroll
                for (int j = 0; j < 8; j++) {
                    mma16816(acc[i][j], ah[i], bh[j]);
                    mma16816(acc[i][j], ah[i], bl[j]);
                    mma16816(acc[i][j], al[i], bh[j]);
                }
        }
        __syncthreads();
    }

    // epilogue: thread owns rows (base, base+8), cols 8j+(lid&3)*2 (+1)
    const float sc = (MODE == 0) ? 0.18033688011112042f : 1.0f;  // 0.125*log2(e)
    #pragma unroll
    for (int i = 0; i < 2; i++) {
        int r = m0 + 32 * wm + 16 * i + (lid >> 2);
        #pragma unroll
        for (int j = 0; j < 8; j++) {
            int c = 8 * j + (lid & 3) * 2;
            int ng = n0 + 64 * wn + c;
            float b0 = bias[ng], b1 = bias[ng + 1];
            #pragma unroll
            for (int hrow = 0; hrow < 2; hrow++) {
                int rr = r + hrow * 8;
                float f0 = (acc[i][j][2*hrow]   + b0) * sc;
                float f1 = (acc[i][j][2*hrow+1] + b1) * sc;
                if (MODE == 3) {
                    Yf[(size_t)rr * DMODEL + ng] = f0;
                    Yf[(size_t)rr * DMODEL + ng + 1] = f1;
                } else {
                    int head = (n0 >> 6) + 2 * 0 + wn + (n0 ? 0 : 0);  // head = ng/64
                    head = ng >> 6;
                    uint32_t hp = pack_bf16(f0, f1);
                    __nv_bfloat162 u = *(__nv_bfloat162*)&hp;
                    size_t dst = (((size_t)head * S_LEN + rr) * DK + (c & 63));
                    *(uint32_t*)(Yh + dst) = hp;
                    *(uint32_t*)(Yl + dst) = pack_bf16(f0 - __bfloat162float(u.x),
                                                       f1 - __bfloat162float(u.y));
                }
            }
        }
    }
}

// flash attention: CTA=(head, 128 q rows), 8 warps (16 rows each), Bc=64.
#define QS 72
#define AT_SMEM ((128*QS*2 + 64*QS*4) * 2)  // Q hi/lo + K,V hi/lo, bf16
__global__ void __launch_bounds__(256) attn_tc(
    const __nv_bfloat16* __restrict__ Qh, const __nv_bfloat16* __restrict__ Ql,
    const __nv_bfloat16* __restrict__ Kh, const __nv_bfloat16* __restrict__ Kl,
    const __nv_bfloat16* __restrict__ Vh, const __nv_bfloat16* __restrict__ Vl,
    __nv_bfloat16* __restrict__ Ah, __nv_bfloat16* __restrict__ Al)
{
    extern __shared__ __nv_bfloat16 sm[];
    __nv_bfloat16 (*Qhs)[QS] = (__nv_bfloat16(*)[QS])sm;
    __nv_bfloat16 (*Qls)[QS] = Qhs + 128;
    __nv_bfloat16 (*Khs)[QS] = Qls + 128;
    __nv_bfloat16 (*Kls)[QS] = Khs + 64;
    __nv_bfloat16 (*Vhs)[QS] = Kls + 64;
    __nv_bfloat16 (*Vls)[QS] = Vhs + 64;

    const int tid = threadIdx.x, w = tid >> 5, lid = tid & 31;
    const int h = blockIdx.y, q0 = blockIdx.x * 128;

    #pragma unroll
    for (int i = 0; i < 4; i++) {              // Q: 1024 uint4
        int idx = tid + i * 256;
        int r = idx >> 3, c8 = (idx & 7) * 8;
        size_t src = ((size_t)h * S_LEN + q0 + r) * DK + c8;
        *(uint4*)&Qhs[r][c8] = *(const uint4*)(Qh + src);
        *(uint4*)&Qls[r][c8] = *(const uint4*)(Ql + src);
    }

    float O[8][4] = {};
    float m0r = -INFINITY, m1r = -INFINITY, l0r = 0.f, l1r = 0.f;

    for (int kv0 = 0; kv0 < S_LEN; kv0 += 64) {
        #pragma unroll
        for (int i = 0; i < 2; i++) {          // K,V: 512 uint4 each
            int idx = tid + i * 256;
            int r = idx >> 3, c8 = (idx & 7) * 8;
            size_t src = ((size_t)h * S_LEN + kv0 + r) * DK + c8;
            *(uint4*)&Khs[r][c8] = *(const uint4*)(Kh + src);
            *(uint4*)&Kls[r][c8] = *(const uint4*)(Kl + src);
            *(uint4*)&Vhs[r][c8] = *(const uint4*)(Vh + src);
            *(uint4*)&Vls[r][c8] = *(const uint4*)(Vl + src);
        }
        __syncthreads();

        // S = Q K^T  (rows 16w..16w+15, cols 0..63)
        float s[8][4] = {};
        #pragma unroll
        for (int ks = 0; ks < 4; ks++) {
            const int ac = 16 * ks + ((lid >> 4) << 3);
            uint32_t ahf[4], alf[4], bh[8][2], bl[8][2], r4[4];
            ldsm4(ahf, smem_u32(&Qhs[16 * w + (lid & 15)][ac]));
            ldsm4(alf, smem_u32(&Qls[16 * w + (lid & 15)][ac]));
            #pragma unroll
            for (int jp = 0; jp < 4; jp++) {
                int rB = 16 * jp + (lid & 15);
                ldsm4(r4, smem_u32(&Khs[rB][ac]));
                bh[2*jp][0]=r4[0]; bh[2*jp][1]=r4[2]; bh[2*jp+1][0]=r4[1]; bh[2*jp+1][1]=r4[3];
                ldsm4(r4, smem_u32(&Kls[rB][ac]));
                bl[2*jp][0]=r4[0]; bl[2*jp][1]=r4[2]; bl[2*jp+1][0]=r4[1]; bl[2*jp+1][1]=r4[3];
            }
            #pragma unroll
            for (int j = 0; j < 8; j++) {
                mma16816(s[j], ahf, bh[j]);
                mma16816(s[j], ahf, bl[j]);
                mma16816(s[j], alf, bh[j]);
            }
        }

        // online softmax (log2 domain; scale folded into Q)
        float rm0 = -INFINITY, rm1 = -INFINITY;
        #pragma unroll
        for (int j = 0; j < 8; j++) {
            rm0 = fmaxf(rm0, fmaxf(s[j][0], s[j][1]));
            rm1 = fmaxf(rm1, fmaxf(s[j][2], s[j][3]));
        }
        rm0 = fmaxf(rm0, __shfl_xor_sync(~0u, rm0, 1)); rm0 = fmaxf(rm0, __shfl_xor_sync(~0u, rm0, 2));
        rm1 = fmaxf(rm1, __shfl_xor_sync(~0u, rm1, 1)); rm1 = fmaxf(rm1, __shfl_xor_sync(~0u, rm1, 2));
        float mn0 = fmaxf(m0r, rm0), mn1 = fmaxf(m1r, rm1);
        float c0 = ex2f(m0r - mn0), c1 = ex2f(m1r - mn1);
        m0r = mn0; m1r = mn1;
        float s0 = 0.f, s1 = 0.f;
        #pragma unroll
        for (int j = 0; j < 8; j++) {
            s[j][0] = ex2f(s[j][0] - mn0); s[j][1] = ex2f(s[j][1] - mn0);
            s[j][2] = ex2f(s[j][2] - mn1); s[j][3] = ex2f(s[j][3] - mn1);
            s0 += s[j][0] + s[j][1]; s1 += s[j][2] + s[j][3];
        }
        s0 += __shfl_xor_sync(~0u, s0, 1); s0 += __shfl_xor_sync(~0u, s0, 2);
        s1 += __shfl_xor_sync(~0u, s1, 1); s1 += __shfl_xor_sync(~0u, s1, 2);
        l0r = l0r * c0 + s0; l1r = l1r * c1 + s1;
        #pragma unroll
        for (int j = 0; j < 8; j++) { O[j][0] *= c0; O[j][1] *= c0; O[j][2] *= c1; O[j][3] *= c1; }

        // P -> bf16 hi/lo A-fragments (S d-frag layout == A frag layout)
        uint32_t ph[4][4], pl[4][4];
        #pragma unroll
        for (int j2 = 0; j2 < 4; j2++) {
            int t0 = 2 * j2, t1 = t0 + 1;
            ph[j2][0] = pack_bf16(s[t0][0], s[t0][1]); ph[j2][1] = pack_bf16(s[t0][2], s[t0][3]);
            ph[j2][2] = pack_bf16(s[t1][0], s[t1][1]); ph[j2][3] = pack_bf16(s[t1][2], s[t1][3]);
            #pragma unroll
            for (int q = 0; q < 4; q++) {
                __nv_bfloat162 u = *(__nv_bfloat162*)&ph[j2][q];
                const float* sv = (q < 2) ? s[t0] : s[t1];
                int b = (q & 1) * 2;
                pl[j2][q] = pack_bf16(sv[b] - __bfloat162float(u.x),
                                      sv[b + 1] - __bfloat162float(u.y));
            }
        }

        // O += P V   (k = kv, V rows [kv][dk] via ldmatrix.trans)
        #pragma unroll
        for (int j2 = 0; j2 < 4; j2++) {
            uint32_t vh[8][2], vl[8][2], r4[4];
            #pragma unroll
            for (int np = 0; np < 4; np++) {
                int rV = 16 * j2 + (lid & 15), cV = 16 * np + ((lid >> 4) << 3);
                ldsm4t(r4, smem_u32(&Vhs[rV][cV]));
                vh[2*np][0]=r4[0]; vh[2*np][1]=r4[1]; vh[2*np+1][0]=r4[2]; vh[2*np+1][1]=r4[3];
                ldsm4t(r4, smem_u32(&Vls[rV][cV]));
                vl[2*np][0]=r4[0]; vl[2*np][1]=r4[1]; vl[2*np+1][0]=r4[2]; vl[2*np+1][1]=r4[3];
            }
            #pragma unroll
            for (int t = 0; t < 8; t++) {
                mma16816(O[t], ph[j2], vh[t]);
                mma16816(O[t], ph[j2], vl[t]);
                mma16816(O[t], pl[j2], vh[t]);
            }
        }
        __syncthreads();
    }

    // normalize + write bf16 hi/lo concat [s][768]
    float i0 = 1.f / l0r, i1 = 1.f / l1r;
    #pragma unroll
    for (int t = 0; t < 8; t++) {
        int c = h * DK + 8 * t + (lid & 3) * 2;
        int r0 = q0 + 16 * w + (lid >> 2);
        #pragma unroll
        for (int hrow = 0; hrow < 2; hrow++) {
            float f0 = O[t][2*hrow]   * (hrow ? i1 : i0);
            float f1 = O[t][2*hrow+1] * (hrow ? i1 : i0);
            uint32_t hp = pack_bf16(f0, f1);
            __nv_bfloat162 u = *(__nv_bfloat162*)&hp;
            size_t dst = (size_t)(r0 + hrow * 8) * DMODEL + c;
            *(uint32_t*)(Ah + dst) = hp;
            *(uint32_t*)(Al + dst) = pack_bf16(f0 - __bfloat162float(u.x),
                                               f1 - __bfloat162float(u.y));
        }
    }
}

extern "C" void kernel_launch(void* const* d_in, const int* in_sizes, int n_in,
                              void* d_out, int out_size)
{
    const float* q  = (const float*)d_in[0];
    const float* k  = (const float*)d_in[1];
    const float* v  = (const float*)d_in[2];
    const float* Wq = (const float*)d_in[3];
    const float* bq = (const float*)d_in[4];
    const float* Wo = (const float*)d_in[5];
    const float* bo = (const float*)d_in[6];
    float* out = (float*)d_out;

    __nv_bfloat16 *xh, *xl, *wh, *wl, *qh, *ql, *kh, *kl, *vh, *vl, *ah, *al;
    cudaGetSymbolAddress((void**)&xh, g_xh); cudaGetSymbolAddress((void**)&xl, g_xl);
    cudaGetSymbolAddress((void**)&wh, g_wh); cudaGetSymbolAddress((void**)&wl, g_wl);
    cudaGetSymbolAddress((void**)&qh, g_qh); cudaGetSymbolAddress((void**)&ql, g_ql);
    cudaGetSymbolAddress((void**)&kh, g_kh); cudaGetSymbolAddress((void**)&kl, g_kl);
    cudaGetSymbolAddress((void**)&vh, g_vh); cudaGetSymbolAddress((void**)&vl, g_vl);
    cudaGetSymbolAddress((void**)&ah, g_ah); cudaGetSymbolAddress((void**)&al, g_al);

    cudaFuncSetAttribute(attn_tc, cudaFuncAttributeMaxDynamicSharedMemorySize, AT_SMEM);

    conv_hilo<<<XN / 4 / 256, 256>>>(q, xh,          xl,          XN / 4);
    conv_hilo<<<XN / 4 / 256, 256>>>(k, xh + XN,     xl + XN,     XN / 4);
    conv_hilo<<<XN / 4 / 256, 256>>>(v, xh + 2 * XN, xl + 2 * XN, XN / 4);
    conv_hilo<<<WN / 4 / 256, 256>>>(Wq, wh,      wl,      WN / 4);
    conv_hilo<<<WN / 4 / 256, 256>>>(Wo, wh + WN, wl + WN, WN / 4);

    dim3 gproj(DMODEL / 128, S_LEN / 128);  // 6 x 32
    proj_tc<0><<<gproj, 256>>>(xh,          xl,          wh, wl, bq, qh, ql, nullptr);
    proj_tc<1><<<gproj, 256>>>(xh + XN,     xl + XN,     wh, wl, bq, kh, kl, nullptr);
    proj_tc<1><<<gproj, 256>>>(xh + 2 * XN, xl + 2 * XN, wh, wl, bq, vh, vl, nullptr);

    dim3 gattn(S_LEN / 128, NH);            // 32 x 12
    attn_tc<<<gattn, 256, AT_SMEM>>>(qh, ql, kh, kl, vh, vl, ah, al);

    proj_tc<3><<<gproj, 256>>>(ah, al, wh + WN, wl + WN, bo, nullptr, nullptr, out);
}

// round 7
// speedup vs baseline: 2.8158x; 1.1214x over previous
#include <cuda_runtime.h>
#include <cuda_bf16.h>
#include <math.h>
#include <stdint.h>

#define S_LEN 4096
#define DMODEL 768
#define NH 12
#define DK 64
#define XN (S_LEN * DMODEL)

__device__ __nv_bfloat16 g_qh[XN], g_ql[XN], g_kh[XN], g_kl[XN], g_vh[XN], g_vl[XN];
__device__ __nv_bfloat16 g_ah[XN], g_al[XN];

__device__ __forceinline__ uint32_t smem_u32(const void* p) {
    uint32_t a;
    asm("{ .reg .u64 t; cvta.to.shared.u64 t, %1; cvt.u32.u64 %0, t; }" : "=r"(a) : "l"(p));
    return a;
}
__device__ __forceinline__ float ex2f(float x) {
    float r; asm("ex2.approx.ftz.f32 %0, %1;" : "=f"(r) : "f"(x)); return r;
}
__device__ __forceinline__ uint32_t pack_bf16(float a, float b) {  // low=a, high=b
    uint32_t r; asm("cvt.rn.satfinite.bf16x2.f32 %0, %1, %2;" : "=r"(r) : "f"(b), "f"(a)); return r;
}
__device__ __forceinline__ void ldsm4(uint32_t* r, uint32_t a) {
    asm volatile("ldmatrix.sync.aligned.m8n8.x4.shared.b16 {%0,%1,%2,%3}, [%4];"
                 : "=r"(r[0]), "=r"(r[1]), "=r"(r[2]), "=r"(r[3]) : "r"(a));
}
__device__ __forceinline__ void ldsm4t(uint32_t* r, uint32_t a) {
    asm volatile("ldmatrix.sync.aligned.m8n8.x4.trans.shared.b16 {%0,%1,%2,%3}, [%4];"
                 : "=r"(r[0]), "=r"(r[1]), "=r"(r[2]), "=r"(r[3]) : "r"(a));
}
__device__ __forceinline__ void mma16816(float* d, const uint32_t* a, const uint32_t* b) {
    asm volatile("mma.sync.aligned.m16n8k16.row.col.f32.bf16.bf16.f32 "
                 "{%0,%1,%2,%3}, {%4,%5,%6,%7}, {%8,%9}, {%0,%1,%2,%3};"
                 : "+f"(d[0]), "+f"(d[1]), "+f"(d[2]), "+f"(d[3])
                 : "r"(a[0]), "r"(a[1]), "r"(a[2]), "r"(a[3]), "r"(b[0]), "r"(b[1]));
}
__device__ __forceinline__ void cp16(uint32_t d, const void* s) {
    asm volatile("cp.async.cg.shared.global [%0], [%1], 16;" :: "r"(d), "l"(s));
}
#define CP_COMMIT() asm volatile("cp.async.commit_group;" ::: "memory")
#define CP_WAIT0()  asm volatile("cp.async.wait_group 0;" ::: "memory")

// split 8 fp32 (two float4) into hi/lo bf16 uint4s
__device__ __forceinline__ void split8(const float4& v0, const float4& v1, uint4& hi, uint4& lo) {
    hi.x = pack_bf16(v0.x, v0.y); hi.y = pack_bf16(v0.z, v0.w);
    hi.z = pack_bf16(v1.x, v1.y); hi.w = pack_bf16(v1.z, v1.w);
    __nv_bfloat162 a = *(__nv_bfloat162*)&hi.x, b = *(__nv_bfloat162*)&hi.y;
    __nv_bfloat162 c = *(__nv_bfloat162*)&hi.z, d = *(__nv_bfloat162*)&hi.w;
    lo.x = pack_bf16(v0.x - __bfloat162float(a.x), v0.y - __bfloat162float(a.y));
    lo.y = pack_bf16(v0.z - __bfloat162float(b.x), v0.w - __bfloat162float(b.y));
    lo.z = pack_bf16(v1.x - __bfloat162float(c.x), v1.y - __bfloat162float(c.y));
    lo.w = pack_bf16(v1.z - __bfloat162float(d.x), v1.w - __bfloat162float(d.y));
}

// ---------------------------------------------------------------------------
// QKV projection, one launch: z=0/1/2 -> q/k/v. fp32 X,W converted in-kernel.
// Y[m,n] = sum X[m,k] W[n,k] + b[n]; 128x128 tile, KCH=32, 3-pass hi/lo MMA.
// Output bf16 hi/lo in [head][s][64]; z==0 pre-scaled by 0.125*log2(e).
// ---------------------------------------------------------------------------
__global__ void __launch_bounds__(256) qkv_proj(
    const float* __restrict__ xq, const float* __restrict__ xk, const float* __restrict__ xv,
    const float* __restrict__ W, const float* __restrict__ bias,
    __nv_bfloat16* __restrict__ Qh, __nv_bfloat16* __restrict__ Ql,
    __nv_bfloat16* __restrict__ Kh, __nv_bfloat16* __restrict__ Kl,
    __nv_bfloat16* __restrict__ Vh, __nv_bfloat16* __restrict__ Vl)
{
    __shared__ __nv_bfloat16 Ahs[128][40], Als[128][40], Bhs[128][40], Bls[128][40];
    const int tid = threadIdx.x, w = tid >> 5, lid = tid & 31;
    const int wm = w >> 1, wn = w & 1;
    const int m0 = blockIdx.y * 128, n0 = blockIdx.x * 128, z = blockIdx.z;
    const float* X = (z == 0) ? xq : (z == 1) ? xk : xv;
    __nv_bfloat16* Yh = (z == 0) ? Qh : (z == 1) ? Kh : Vh;
    __nv_bfloat16* Yl = (z == 0) ? Ql : (z == 1) ? Kl : Vl;
    const float sc = (z == 0) ? 0.18033688011112042f : 1.0f;

    float acc[2][8][4] = {};

    for (int k0 = 0; k0 < DMODEL; k0 += 32) {
        #pragma unroll
        for (int i = 0; i < 2; i++) {
            int idx = tid + i * 256;             // 512 8-elem chunks per matrix
            int r = idx >> 2, c8 = (idx & 3) * 8;
            uint4 hi, lo;
            const float* xs = X + (size_t)(m0 + r) * DMODEL + k0 + c8;
            split8(*(const float4*)xs, *(const float4*)(xs + 4), hi, lo);
            *(uint4*)&Ahs[r][c8] = hi; *(uint4*)&Als[r][c8] = lo;
            const float* ws = W + (size_t)(n0 + r) * DMODEL + k0 + c8;
            split8(*(const float4*)ws, *(const float4*)(ws + 4), hi, lo);
            *(uint4*)&Bhs[r][c8] = hi; *(uint4*)&Bls[r][c8] = lo;
        }
        __syncthreads();
        #pragma unroll
        for (int ks = 0; ks < 32; ks += 16) {
            const int ac = ks + ((lid >> 4) << 3);
            uint32_t ah[2][4], al[2][4], bh[8][2], bl[8][2], r4[4];
            #pragma unroll
            for (int jp = 0; jp < 4; jp++) {
                int rB = 64 * wn + 16 * jp + (lid & 15);
                ldsm4(r4, smem_u32(&Bhs[rB][ac]));
                bh[2*jp][0]=r4[0]; bh[2*jp][1]=r4[2]; bh[2*jp+1][0]=r4[1]; bh[2*jp+1][1]=r4[3];
                ldsm4(r4, smem_u32(&Bls[rB][ac]));
                bl[2*jp][0]=r4[0]; bl[2*jp][1]=r4[2]; bl[2*jp+1][0]=r4[1]; bl[2*jp+1][1]=r4[3];
            }
            #pragma unroll
            for (int i = 0; i < 2; i++) {
                int rA = 32 * wm + 16 * i + (lid & 15);
                ldsm4(ah[i], smem_u32(&Ahs[rA][ac]));
                ldsm4(al[i], smem_u32(&Als[rA][ac]));
            }
            #pragma unroll
            for (int i = 0; i < 2; i++)
                #pragma unroll
                for (int j = 0; j < 8; j++) {
                    mma16816(acc[i][j], ah[i], bh[j]);
                    mma16816(acc[i][j], ah[i], bl[j]);
                    mma16816(acc[i][j], al[i], bh[j]);
                }
        }
        __syncthreads();
    }

    #pragma unroll
    for (int i = 0; i < 2; i++) {
        int r = m0 + 32 * wm + 16 * i + (lid >> 2);
        #pragma unroll
        for (int j = 0; j < 8; j++) {
            int c = 8 * j + (lid & 3) * 2;
            int ng = n0 + 64 * wn + c;
            float b0 = bias[ng], b1 = bias[ng + 1];
            int head = ng >> 6;
            #pragma unroll
            for (int hrow = 0; hrow < 2; hrow++) {
                int rr = r + hrow * 8;
                float f0 = (acc[i][j][2*hrow]   + b0) * sc;
                float f1 = (acc[i][j][2*hrow+1] + b1) * sc;
                uint32_t hp = pack_bf16(f0, f1);
                __nv_bfloat162 u = *(__nv_bfloat162*)&hp;
                size_t dst = ((size_t)head * S_LEN + rr) * DK + (ng & 63);
                *(uint32_t*)(Yh + dst) = hp;
                *(uint32_t*)(Yl + dst) = pack_bf16(f0 - __bfloat162float(u.x),
                                                   f1 - __bfloat162float(u.y));
            }
        }
    }
}

// ---------------------------------------------------------------------------
// Output projection: A (bf16 hi/lo from attention) @ Wo^T + bo -> fp32 out.
// ---------------------------------------------------------------------------
__global__ void __launch_bounds__(256) out_proj(
    const __nv_bfloat16* __restrict__ Xh, const __nv_bfloat16* __restrict__ Xl,
    const float* __restrict__ W, const float* __restrict__ bias, float* __restrict__ Yf)
{
    __shared__ __nv_bfloat16 Ahs[128][40], Als[128][40], Bhs[128][40], Bls[128][40];
    const int tid = threadIdx.x, w = tid >> 5, lid = tid & 31;
    const int wm = w >> 1, wn = w & 1;
    const int m0 = blockIdx.y * 128, n0 = blockIdx.x * 128;

    float acc[2][8][4] = {};

    for (int k0 = 0; k0 < DMODEL; k0 += 32) {
        #pragma unroll
        for (int i = 0; i < 2; i++) {
            int idx = tid + i * 256;
            int r = idx >> 2, c8 = (idx & 3) * 8;
            size_t xs = (size_t)(m0 + r) * DMODEL + k0 + c8;
            *(uint4*)&Ahs[r][c8] = *(const uint4*)(Xh + xs);
            *(uint4*)&Als[r][c8] = *(const uint4*)(Xl + xs);
            uint4 hi, lo;
            const float* ws = W + (size_t)(n0 + r) * DMODEL + k0 + c8;
            split8(*(const float4*)ws, *(const float4*)(ws + 4), hi, lo);
            *(uint4*)&Bhs[r][c8] = hi; *(uint4*)&Bls[r][c8] = lo;
        }
        __syncthreads();
        #pragma unroll
        for (int ks = 0; ks < 32; ks += 16) {
            const int ac = ks + ((lid >> 4) << 3);
            uint32_t ah[2][4], al[2][4], bh[8][2], bl[8][2], r4[4];
            #pragma unroll
            for (int jp = 0; jp < 4; jp++) {
                int rB = 64 * wn + 16 * jp + (lid & 15);
                ldsm4(r4, smem_u32(&Bhs[rB][ac]));
                bh[2*jp][0]=r4[0]; bh[2*jp][1]=r4[2]; bh[2*jp+1][0]=r4[1]; bh[2*jp+1][1]=r4[3];
                ldsm4(r4, smem_u32(&Bls[rB][ac]));
                bl[2*jp][0]=r4[0]; bl[2*jp][1]=r4[2]; bl[2*jp+1][0]=r4[1]; bl[2*jp+1][1]=r4[3];
            }
            #pragma unroll
            for (int i = 0; i < 2; i++) {
                int rA = 32 * wm + 16 * i + (lid & 15);
                ldsm4(ah[i], smem_u32(&Ahs[rA][ac]));
                ldsm4(al[i], smem_u32(&Als[rA][ac]));
            }
            #pragma unroll
            for (int i = 0; i < 2; i++)
                #pragma unroll
                for (int j = 0; j < 8; j++) {
                    mma16816(acc[i][j], ah[i], bh[j]);
                    mma16816(acc[i][j], ah[i], bl[j]);
                    mma16816(acc[i][j], al[i], bh[j]);
                }
        }
        __syncthreads();
    }

    #pragma unroll
    for (int i = 0; i < 2; i++) {
        int r = m0 + 32 * wm + 16 * i + (lid >> 2);
        #pragma unroll
        for (int j = 0; j < 8; j++) {
            int ng = n0 + 64 * wn + 8 * j + (lid & 3) * 2;
            float b0 = bias[ng], b1 = bias[ng + 1];
            #pragma unroll
            for (int hrow = 0; hrow < 2; hrow++) {
                int rr = r + hrow * 8;
                Yf[(size_t)rr * DMODEL + ng]     = acc[i][j][2*hrow]   + b0;
                Yf[(size_t)rr * DMODEL + ng + 1] = acc[i][j][2*hrow+1] + b1;
            }
        }
    }
}

// ---------------------------------------------------------------------------
// Flash attention: CTA=(head, 128 q rows), 8 warps x 16 rows, Bc=64.
// cp.async double-buffered K/V (2 stages), one __syncthreads per tile.
// ---------------------------------------------------------------------------
#define QS 72
#define AT_SMEM ((256 + 512) * QS * 2)  // Q hi/lo (256 rows) + 2 KV stages (512 rows)
__global__ void __launch_bounds__(256) attn_tc(
    const __nv_bfloat16* __restrict__ Qh, const __nv_bfloat16* __restrict__ Ql,
    const __nv_bfloat16* __restrict__ Kh, const __nv_bfloat16* __restrict__ Kl,
    const __nv_bfloat16* __restrict__ Vh, const __nv_bfloat16* __restrict__ Vl,
    __nv_bfloat16* __restrict__ Ah, __nv_bfloat16* __restrict__ Al)
{
    extern __shared__ __nv_bfloat16 sm[];
    __nv_bfloat16 (*Qhs)[QS] = (__nv_bfloat16(*)[QS])sm;   // 128 rows
    __nv_bfloat16 (*Qls)[QS] = Qhs + 128;
    __nv_bfloat16 (*KV0)[QS] = Qls + 128;                   // stage: K(64) Kl(64) V(64) Vl(64)

    const int tid = threadIdx.x, w = tid >> 5, lid = tid & 31;
    const int h = blockIdx.y, q0 = blockIdx.x * 128;

    #pragma unroll
    for (int i = 0; i < 4; i++) {              // Q: 1024 uint4
        int idx = tid + i * 256;
        int r = idx >> 3, c8 = (idx & 7) * 8;
        size_t src = ((size_t)h * S_LEN + q0 + r) * DK + c8;
        *(uint4*)&Qhs[r][c8] = *(const uint4*)(Qh + src);
        *(uint4*)&Qls[r][c8] = *(const uint4*)(Ql + src);
    }

    // prefetch KV tile 0 into stage 0
    {
        __nv_bfloat16 (*S0)[QS] = KV0;
        #pragma unroll
        for (int i = 0; i < 2; i++) {
            int idx = tid + i * 256;
            int r = idx >> 3, c8 = (idx & 7) * 8;
            size_t src = ((size_t)h * S_LEN + r) * DK + c8;
            cp16(smem_u32(&S0[r][c8]),       Kh + src);
            cp16(smem_u32(&S0[64 + r][c8]),  Kl + src);
            cp16(smem_u32(&S0[128 + r][c8]), Vh + src);
            cp16(smem_u32(&S0[192 + r][c8]), Vl + src);
        }
        CP_COMMIT();
    }

    float O[8][4] = {};
    float m0r = -INFINITY, m1r = -INFINITY, l0r = 0.f, l1r = 0.f;

    for (int t = 0; t < S_LEN / 64; t++) {
        CP_WAIT0();
        __syncthreads();                        // stage t&1 fully resident

        if (t + 1 < S_LEN / 64) {               // prefetch next tile into other stage
            __nv_bfloat16 (*SN)[QS] = KV0 + ((t + 1) & 1) * 256;
            int kvn = (t + 1) * 64;
            #pragma unroll
            for (int i = 0; i < 2; i++) {
                int idx = tid + i * 256;
                int r = idx >> 3, c8 = (idx & 7) * 8;
                size_t src = ((size_t)h * S_LEN + kvn + r) * DK + c8;
                cp16(smem_u32(&SN[r][c8]),       Kh + src);
                cp16(smem_u32(&SN[64 + r][c8]),  Kl + src);
                cp16(smem_u32(&SN[128 + r][c8]), Vh + src);
                cp16(smem_u32(&SN[192 + r][c8]), Vl + src);
            }
            CP_COMMIT();
        }

        __nv_bfloat16 (*Khs)[QS] = KV0 + (t & 1) * 256;
        __nv_bfloat16 (*Kls)[QS] = Khs + 64;
        __nv_bfloat16 (*Vhs)[QS] = Khs + 128;
        __nv_bfloat16 (*Vls)[QS] = Khs + 192;

        // S = Q K^T
        float s[8][4] = {};
        #pragma unroll
        for (int ks = 0; ks < 4; ks++) {
            const int ac = 16 * ks + ((lid >> 4) << 3);
            uint32_t ahf[4], alf[4], bh[8][2], bl[8][2], r4[4];
            ldsm4(ahf, smem_u32(&Qhs[16 * w + (lid & 15)][ac]));
            ldsm4(alf, smem_u32(&Qls[16 * w + (lid & 15)][ac]));
            #pragma unroll
            for (int jp = 0; jp < 4; jp++) {
                int rB = 16 * jp + (lid & 15);
                ldsm4(r4, smem_u32(&Khs[rB][ac]));
                bh[2*jp][0]=r4[0]; bh[2*jp][1]=r4[2]; bh[2*jp+1][0]=r4[1]; bh[2*jp+1][1]=r4[3];
                ldsm4(r4, smem_u32(&Kls[rB][ac]));
                bl[2*jp][0]=r4[0]; bl[2*jp][1]=r4[2]; bl[2*jp+1][0]=r4[1]; bl[2*jp+1][1]=r4[3];
            }
            #pragma unroll
            for (int j = 0; j < 8; j++) {
                mma16816(s[j], ahf, bh[j]);
                mma16816(s[j], ahf, bl[j]);
                mma16816(s[j], alf, bh[j]);
            }
        }

        // online softmax (log2 domain)
        float rm0 = -INFINITY, rm1 = -INFINITY;
        #pragma unroll
        for (int j = 0; j < 8; j++) {
            rm0 = fmaxf(rm0, fmaxf(s[j][0], s[j][1]));
            rm1 = fmaxf(rm1, fmaxf(s[j][2], s[j][3]));
        }
        rm0 = fmaxf(rm0, __shfl_xor_sync(~0u, rm0, 1)); rm0 = fmaxf(rm0, __shfl_xor_sync(~0u, rm0, 2));
        rm1 = fmaxf(rm1, __shfl_xor_sync(~0u, rm1, 1)); rm1 = fmaxf(rm1, __shfl_xor_sync(~0u, rm1, 2));
        float mn0 = fmaxf(m0r, rm0), mn1 = fmaxf(m1r, rm1);
        float c0 = ex2f(m0r - mn0), c1 = ex2f(m1r - mn1);
        m0r = mn0; m1r = mn1;
        float s0 = 0.f, s1 = 0.f;
        #pragma unroll
        for (int j = 0; j < 8; j++) {
            s[j][0] = ex2f(s[j][0] - mn0); s[j][1] = ex2f(s[j][1] - mn0);
            s[j][2] = ex2f(s[j][2] - mn1); s[j][3] = ex2f(s[j][3] - mn1);
            s0 += s[j][0] + s[j][1]; s1 += s[j][2] + s[j][3];
        }
        s0 += __shfl_xor_sync(~0u, s0, 1); s0 += __shfl_xor_sync(~0u, s0, 2);
        s1 += __shfl_xor_sync(~0u, s1, 1); s1 += __shfl_xor_sync(~0u, s1, 2);
        l0r = l0r * c0 + s0; l1r = l1r * c1 + s1;
        #pragma unroll
        for (int j = 0; j < 8; j++) { O[j][0] *= c0; O[j][1] *= c0; O[j][2] *= c1; O[j][3] *= c1; }

        // P -> bf16 hi/lo A-fragments
        uint32_t ph[4][4], pl[4][4];
        #pragma unroll
        for (int j2 = 0; j2 < 4; j2++) {
            int t0 = 2 * j2, t1 = t0 + 1;
            ph[j2][0] = pack_bf16(s[t0][0], s[t0][1]); ph[j2][1] = pack_bf16(s[t0][2], s[t0][3]);
            ph[j2][2] = pack_bf16(s[t1][0], s[t1][1]); ph[j2][3] = pack_bf16(s[t1][2], s[t1][3]);
            #pragma unroll
            for (int q = 0; q < 4; q++) {
                __nv_bfloat162 u = *(__nv_bfloat162*)&ph[j2][q];
                const float* sv = (q < 2) ? s[t0] : s[t1];
                int b = (q & 1) * 2;
                pl[j2][q] = pack_bf16(sv[b] - __bfloat162float(u.x),
                                      sv[b + 1] - __bfloat162float(u.y));
            }
        }

        // O += P V
        #pragma unroll
        for (int j2 = 0; j2 < 4; j2++) {
            uint32_t vh[8][2], vl[8][2], r4[4];
            #pragma unroll
            for (int np = 0; np < 4; np++) {
                int rV = 16 * j2 + (lid & 15), cV = 16 * np + ((lid >> 4) << 3);
                ldsm4t(r4, smem_u32(&Vhs[rV][cV]));
                vh[2*np][0]=r4[0]; vh[2*np][1]=r4[1]; vh[2*np+1][0]=r4[2]; vh[2*np+1][1]=r4[3];
                ldsm4t(r4, smem_u32(&Vls[rV][cV]));
                vl[2*np][0]=r4[0]; vl[2*np][1]=r4[1]; vl[2*np+1][0]=r4[2]; vl[2*np+1][1]=r4[3];
            }
            #pragma unroll
            for (int tt = 0; tt < 8; tt++) {
                mma16816(O[tt], ph[j2], vh[tt]);
                mma16816(O[tt], ph[j2], vl[tt]);
                mma16816(O[tt], pl[j2], vh[tt]);
            }
        }
    }

    // normalize + write bf16 hi/lo concat [s][768]
    float i0 = 1.f / l0r, i1 = 1.f / l1r;
    #pragma unroll
    for (int t = 0; t < 8; t++) {
        int c = h * DK + 8 * t + (lid & 3) * 2;
        int r0 = q0 + 16 * w + (lid >> 2);
        #pragma unroll
        for (int hrow = 0; hrow < 2; hrow++) {
            float f0 = O[t][2*hrow]   * (hrow ? i1 : i0);
            float f1 = O[t][2*hrow+1] * (hrow ? i1 : i0);
            uint32_t hp = pack_bf16(f0, f1);
            __nv_bfloat162 u = *(__nv_bfloat162*)&hp;
            size_t dst = (size_t)(r0 + hrow * 8) * DMODEL + c;
            *(uint32_t*)(Ah + dst) = hp;
            *(uint32_t*)(Al + dst) = pack_bf16(f0 - __bfloat162float(u.x),
                                               f1 - __bfloat162float(u.y));
        }
    }
}

extern "C" void kernel_launch(void* const* d_in, const int* in_sizes, int n_in,
                              void* d_out, int out_size)
{
    const float* q  = (const float*)d_in[0];
    const float* k  = (const float*)d_in[1];
    const float* v  = (const float*)d_in[2];
    const float* Wq = (const float*)d_in[3];
    const float* bq = (const float*)d_in[4];
    const float* Wo = (const float*)d_in[5];
    const float* bo = (const float*)d_in[6];
    float* out = (float*)d_out;

    __nv_bfloat16 *qh, *ql, *kh, *kl, *vh, *vl, *ah, *al;
    cudaGetSymbolAddress((void**)&qh, g_qh); cudaGetSymbolAddress((void**)&ql, g_ql);
    cudaGetSymbolAddress((void**)&kh, g_kh); cudaGetSymbolAddress((void**)&kl, g_kl);
    cudaGetSymbolAddress((void**)&vh, g_vh); cudaGetSymbolAddress((void**)&vl, g_vl);
    cudaGetSymbolAddress((void**)&ah, g_ah); cudaGetSymbolAddress((void**)&al, g_al);

    cudaFuncSetAttribute(attn_tc, cudaFuncAttributeMaxDynamicSharedMemorySize, AT_SMEM);

    dim3 gqkv(DMODEL / 128, S_LEN / 128, 3);   // 6 x 32 x 3
    qkv_proj<<<gqkv, 256>>>(q, k, v, Wq, bq, qh, ql, kh, kl, vh, vl);

    dim3 gattn(S_LEN / 128, NH);               // 32 x 12
    attn_tc<<<gattn, 256, AT_SMEM>>>(qh, ql, kh, kl, vh, vl, ah, al);

    dim3 gout(DMODEL / 128, S_LEN / 128);      // 6 x 32
    out_proj<<<gout, 256>>>(ah, al, Wo, bo, out);
}

// round 8
// speedup vs baseline: 3.0448x; 1.0813x over previous
#include <cuda_runtime.h>
#include <cuda_bf16.h>
#include <math.h>
#include <stdint.h>

#define S_LEN 4096
#define DMODEL 768
#define NH 12
#define DK 64
#define XN (S_LEN * DMODEL)
#define WN (DMODEL * DMODEL)

__device__ __nv_bfloat16 g_xh[3 * XN], g_xl[3 * XN];      // q,k,v inputs hi/lo
__device__ __nv_bfloat16 g_wh[2 * WN], g_wl[2 * WN];      // Wq, Wo hi/lo
__device__ __nv_bfloat16 g_qh[XN], g_ql[XN], g_kh[XN], g_kl[XN], g_vh[XN], g_vl[XN];
__device__ __nv_bfloat16 g_ah[XN], g_al[XN];

__device__ __forceinline__ uint32_t smem_u32(const void* p) {
    uint32_t a;
    asm("{ .reg .u64 t; cvta.to.shared.u64 t, %1; cvt.u32.u64 %0, t; }" : "=r"(a) : "l"(p));
    return a;
}
__device__ __forceinline__ float ex2f(float x) {
    float r; asm("ex2.approx.ftz.f32 %0, %1;" : "=f"(r) : "f"(x)); return r;
}
__device__ __forceinline__ uint32_t pack_bf16(float a, float b) {  // low=a, high=b
    uint32_t r; asm("cvt.rn.satfinite.bf16x2.f32 %0, %1, %2;" : "=r"(r) : "f"(b), "f"(a)); return r;
}
__device__ __forceinline__ void ldsm4(uint32_t* r, uint32_t a) {
    asm volatile("ldmatrix.sync.aligned.m8n8.x4.shared.b16 {%0,%1,%2,%3}, [%4];"
                 : "=r"(r[0]), "=r"(r[1]), "=r"(r[2]), "=r"(r[3]) : "r"(a));
}
__device__ __forceinline__ void ldsm4t(uint32_t* r, uint32_t a) {
    asm volatile("ldmatrix.sync.aligned.m8n8.x4.trans.shared.b16 {%0,%1,%2,%3}, [%4];"
                 : "=r"(r[0]), "=r"(r[1]), "=r"(r[2]), "=r"(r[3]) : "r"(a));
}
__device__ __forceinline__ void mma16816(float* d, const uint32_t* a, const uint32_t* b) {
    asm volatile("mma.sync.aligned.m16n8k16.row.col.f32.bf16.bf16.f32 "
                 "{%0,%1,%2,%3}, {%4,%5,%6,%7}, {%8,%9}, {%0,%1,%2,%3};"
                 : "+f"(d[0]), "+f"(d[1]), "+f"(d[2]), "+f"(d[3])
                 : "r"(a[0]), "r"(a[1]), "r"(a[2]), "r"(a[3]), "r"(b[0]), "r"(b[1]));
}
__device__ __forceinline__ void cp16(uint32_t d, const void* s) {
    asm volatile("cp.async.cg.shared.global [%0], [%1], 16;" :: "r"(d), "l"(s));
}
#define CP_COMMIT() asm volatile("cp.async.commit_group;" ::: "memory")
#define CP_WAIT0()  asm volatile("cp.async.wait_group 0;" ::: "memory")

__global__ void conv_hilo(const float* __restrict__ in, __nv_bfloat16* __restrict__ hi,
                          __nv_bfloat16* __restrict__ lo, int n4)
{
    int i = blockIdx.x * blockDim.x + threadIdx.x;
    if (i >= n4) return;
    float4 v = ((const float4*)in)[i];
    uint32_t h01 = pack_bf16(v.x, v.y), h23 = pack_bf16(v.z, v.w);
    __nv_bfloat162 a = *(__nv_bfloat162*)&h01, b = *(__nv_bfloat162*)&h23;
    ((uint32_t*)hi)[2 * i] = h01; ((uint32_t*)hi)[2 * i + 1] = h23;
    ((uint32_t*)lo)[2 * i]     = pack_bf16(v.x - __bfloat162float(a.x), v.y - __bfloat162float(a.y));
    ((uint32_t*)lo)[2 * i + 1] = pack_bf16(v.z - __bfloat162float(b.x), v.w - __bfloat162float(b.y));
}

// ---------------------------------------------------------------------------
// GEMM core (shared by both projections): bf16 hi/lo inputs from gmem,
// cp.async 2-stage pipeline over KCH=32 chunks, 128x128 tile, 8 warps.
// Dynamic smem: 2 stages x [Ah|Al|Bh|Bl], each 128x40 bf16.
// ---------------------------------------------------------------------------
#define PM 5120                       // elems per matrix (128*40)
#define PSTG (4 * PM)                 // elems per stage
#define PROJ_SMEM (2 * PSTG * 2)      // bytes (81920)

__device__ __forceinline__ void proj_stage_load(
    __nv_bfloat16* st, const __nv_bfloat16* Xh, const __nv_bfloat16* Xl,
    const __nv_bfloat16* Wh, const __nv_bfloat16* Wl,
    int m0, int n0, int k0, int tid)
{
    #pragma unroll
    for (int i = 0; i < 2; i++) {
        int idx = tid + i * 256;
        int r = idx >> 2, c8 = (idx & 3) * 8;
        size_t xs = (size_t)(m0 + r) * DMODEL + k0 + c8;
        size_t ws = (size_t)(n0 + r) * DMODEL + k0 + c8;
        uint32_t base = smem_u32(st + r * 40 + c8);
        cp16(base,               Xh + xs);
        cp16(base + PM * 2,      Xl + xs);
        cp16(base + 2 * PM * 2,  Wh + ws);
        cp16(base + 3 * PM * 2,  Wl + ws);
    }
    CP_COMMIT();
}

__device__ __forceinline__ void proj_gemm(
    float acc[2][8][4], __nv_bfloat16* sm,
    const __nv_bfloat16* Xh, const __nv_bfloat16* Xl,
    const __nv_bfloat16* Wh, const __nv_bfloat16* Wl,
    int m0, int n0, int tid, int wm, int wn, int lid)
{
    proj_stage_load(sm, Xh, Xl, Wh, Wl, m0, n0, 0, tid);
    for (int t = 0; t < DMODEL / 32; t++) {
        CP_WAIT0();
        __syncthreads();
        if (t + 1 < DMODEL / 32)
            proj_stage_load(sm + ((t + 1) & 1) * PSTG, Xh, Xl, Wh, Wl, m0, n0, (t + 1) * 32, tid);
        __nv_bfloat16* Ahs = sm + (t & 1) * PSTG;
        __nv_bfloat16* Als = Ahs + PM;
        __nv_bfloat16* Bhs = Ahs + 2 * PM;
        __nv_bfloat16* Bls = Ahs + 3 * PM;
        #pragma unroll
        for (int ks = 0; ks < 32; ks += 16) {
            const int ac = ks + ((lid >> 4) << 3);
            uint32_t ah[2][4], al[2][4], bh[8][2], bl[8][2], r4[4];
            #pragma unroll
            for (int jp = 0; jp < 4; jp++) {
                int rB = 64 * wn + 16 * jp + (lid & 15);
                ldsm4(r4, smem_u32(Bhs + rB * 40 + ac));
                bh[2*jp][0]=r4[0]; bh[2*jp][1]=r4[2]; bh[2*jp+1][0]=r4[1]; bh[2*jp+1][1]=r4[3];
                ldsm4(r4, smem_u32(Bls + rB * 40 + ac));
                bl[2*jp][0]=r4[0]; bl[2*jp][1]=r4[2]; bl[2*jp+1][0]=r4[1]; bl[2*jp+1][1]=r4[3];
            }
            #pragma unroll
            for (int i = 0; i < 2; i++) {
                int rA = 32 * wm + 16 * i + (lid & 15);
                ldsm4(ah[i], smem_u32(Ahs + rA * 40 + ac));
                ldsm4(al[i], smem_u32(Als + rA * 40 + ac));
            }
            #pragma unroll
            for (int i = 0; i < 2; i++)
                #pragma unroll
                for (int j = 0; j < 8; j++) {
                    mma16816(acc[i][j], ah[i], bh[j]);
                    mma16816(acc[i][j], ah[i], bl[j]);
                    mma16816(acc[i][j], al[i], bh[j]);
                }
        }
        __syncthreads();
    }
}

// QKV projection, one launch, z selects q/k/v. Output [head][s][64] hi/lo.
__global__ void __launch_bounds__(256) qkv_proj(
    const __nv_bfloat16* __restrict__ xh, const __nv_bfloat16* __restrict__ xl,
    const __nv_bfloat16* __restrict__ Wh, const __nv_bfloat16* __restrict__ Wl,
    const float* __restrict__ bias,
    __nv_bfloat16* __restrict__ Qh, __nv_bfloat16* __restrict__ Ql,
    __nv_bfloat16* __restrict__ Kh, __nv_bfloat16* __restrict__ Kl,
    __nv_bfloat16* __restrict__ Vh, __nv_bfloat16* __restrict__ Vl)
{
    extern __shared__ __nv_bfloat16 sm[];
    const int tid = threadIdx.x, w = tid >> 5, lid = tid & 31;
    const int wm = w >> 1, wn = w & 1;
    const int m0 = blockIdx.y * 128, n0 = blockIdx.x * 128, z = blockIdx.z;
    const __nv_bfloat16* Xh = xh + (size_t)z * XN;
    const __nv_bfloat16* Xl = xl + (size_t)z * XN;
    __nv_bfloat16* Yh = (z == 0) ? Qh : (z == 1) ? Kh : Vh;
    __nv_bfloat16* Yl = (z == 0) ? Ql : (z == 1) ? Kl : Vl;
    const float sc = (z == 0) ? 0.18033688011112042f : 1.0f;  // 0.125*log2(e)

    float acc[2][8][4] = {};
    proj_gemm(acc, sm, Xh, Xl, Wh, Wl, m0, n0, tid, wm, wn, lid);

    #pragma unroll
    for (int i = 0; i < 2; i++) {
        int r = m0 + 32 * wm + 16 * i + (lid >> 2);
        #pragma unroll
        for (int j = 0; j < 8; j++) {
            int ng = n0 + 64 * wn + 8 * j + (lid & 3) * 2;
            float b0 = bias[ng], b1 = bias[ng + 1];
            int head = ng >> 6;
            #pragma unroll
            for (int hrow = 0; hrow < 2; hrow++) {
                int rr = r + hrow * 8;
                float f0 = (acc[i][j][2*hrow]   + b0) * sc;
                float f1 = (acc[i][j][2*hrow+1] + b1) * sc;
                uint32_t hp = pack_bf16(f0, f1);
                __nv_bfloat162 u = *(__nv_bfloat162*)&hp;
                size_t dst = ((size_t)head * S_LEN + rr) * DK + (ng & 63);
                *(uint32_t*)(Yh + dst) = hp;
                *(uint32_t*)(Yl + dst) = pack_bf16(f0 - __bfloat162float(u.x),
                                                   f1 - __bfloat162float(u.y));
            }
        }
    }
}

// Output projection: attention out (bf16 hi/lo) @ Wo^T + bo -> fp32.
__global__ void __launch_bounds__(256) out_proj(
    const __nv_bfloat16* __restrict__ Xh, const __nv_bfloat16* __restrict__ Xl,
    const __nv_bfloat16* __restrict__ Wh, const __nv_bfloat16* __restrict__ Wl,
    const float* __restrict__ bias, float* __restrict__ Yf)
{
    extern __shared__ __nv_bfloat16 sm[];
    const int tid = threadIdx.x, w = tid >> 5, lid = tid & 31;
    const int wm = w >> 1, wn = w & 1;
    const int m0 = blockIdx.y * 128, n0 = blockIdx.x * 128;

    float acc[2][8][4] = {};
    proj_gemm(acc, sm, Xh, Xl, Wh, Wl, m0, n0, tid, wm, wn, lid);

    #pragma unroll
    for (int i = 0; i < 2; i++) {
        int r = m0 + 32 * wm + 16 * i + (lid >> 2);
        #pragma unroll
        for (int j = 0; j < 8; j++) {
            int ng = n0 + 64 * wn + 8 * j + (lid & 3) * 2;
            float b0 = bias[ng], b1 = bias[ng + 1];
            #pragma unroll
            for (int hrow = 0; hrow < 2; hrow++) {
                int rr = r + hrow * 8;
                Yf[(size_t)rr * DMODEL + ng]     = acc[i][j][2*hrow]   + b0;
                Yf[(size_t)rr * DMODEL + ng + 1] = acc[i][j][2*hrow+1] + b1;
            }
        }
    }
}

// ---------------------------------------------------------------------------
// Flash attention (unchanged from R7): CTA=(head, 128 q rows), Bc=64,
// cp.async double-buffered K/V.
// ---------------------------------------------------------------------------
#define QS 72
#define AT_SMEM ((256 + 512) * QS * 2)
__global__ void __launch_bounds__(256) attn_tc(
    const __nv_bfloat16* __restrict__ Qh, const __nv_bfloat16* __restrict__ Ql,
    const __nv_bfloat16* __restrict__ Kh, const __nv_bfloat16* __restrict__ Kl,
    const __nv_bfloat16* __restrict__ Vh, const __nv_bfloat16* __restrict__ Vl,
    __nv_bfloat16* __restrict__ Ah, __nv_bfloat16* __restrict__ Al)
{
    extern __shared__ __nv_bfloat16 sm[];
    __nv_bfloat16 (*Qhs)[QS] = (__nv_bfloat16(*)[QS])sm;
    __nv_bfloat16 (*Qls)[QS] = Qhs + 128;
    __nv_bfloat16 (*KV0)[QS] = Qls + 128;

    const int tid = threadIdx.x, w = tid >> 5, lid = tid & 31;
    const int h = blockIdx.y, q0 = blockIdx.x * 128;

    #pragma unroll
    for (int i = 0; i < 4; i++) {
        int idx = tid + i * 256;
        int r = idx >> 3, c8 = (idx & 7) * 8;
        size_t src = ((size_t)h * S_LEN + q0 + r) * DK + c8;
        *(uint4*)&Qhs[r][c8] = *(const uint4*)(Qh + src);
        *(uint4*)&Qls[r][c8] = *(const uint4*)(Ql + src);
    }
    {
        __nv_bfloat16 (*S0)[QS] = KV0;
        #pragma unroll
        for (int i = 0; i < 2; i++) {
            int idx = tid + i * 256;
            int r = idx >> 3, c8 = (idx & 7) * 8;
            size_t src = ((size_t)h * S_LEN + r) * DK + c8;
            cp16(smem_u32(&S0[r][c8]),       Kh + src);
            cp16(smem_u32(&S0[64 + r][c8]),  Kl + src);
            cp16(smem_u32(&S0[128 + r][c8]), Vh + src);
            cp16(smem_u32(&S0[192 + r][c8]), Vl + src);
        }
        CP_COMMIT();
    }

    float O[8][4] = {};
    float m0r = -INFINITY, m1r = -INFINITY, l0r = 0.f, l1r = 0.f;

    for (int t = 0; t < S_LEN / 64; t++) {
        CP_WAIT0();
        __syncthreads();
        if (t + 1 < S_LEN / 64) {
            __nv_bfloat16 (*SN)[QS] = KV0 + ((t + 1) & 1) * 256;
            int kvn = (t + 1) * 64;
            #pragma unroll
            for (int i = 0; i < 2; i++) {
                int idx = tid + i * 256;
                int r = idx >> 3, c8 = (idx & 7) * 8;
                size_t src = ((size_t)h * S_LEN + kvn + r) * DK + c8;
                cp16(smem_u32(&SN[r][c8]),       Kh + src);
                cp16(smem_u32(&SN[64 + r][c8]),  Kl + src);
                cp16(smem_u32(&SN[128 + r][c8]), Vh + src);
                cp16(smem_u32(&SN[192 + r][c8]), Vl + src);
            }
            CP_COMMIT();
        }
        __nv_bfloat16 (*Khs)[QS] = KV0 + (t & 1) * 256;
        __nv_bfloat16 (*Kls)[QS] = Khs + 64;
        __nv_bfloat16 (*Vhs)[QS] = Khs + 128;
        __nv_bfloat16 (*Vls)[QS] = Khs + 192;

        float s[8][4] = {};
        #pragma unroll
        for (int ks = 0; ks < 4; ks++) {
            const int ac = 16 * ks + ((lid >> 4) << 3);
            uint32_t ahf[4], alf[4], bh[8][2], bl[8][2], r4[4];
            ldsm4(ahf, smem_u32(&Qhs[16 * w + (lid & 15)][ac]));
            ldsm4(alf, smem_u32(&Qls[16 * w + (lid & 15)][ac]));
            #pragma unroll
            for (int jp = 0; jp < 4; jp++) {
                int rB = 16 * jp + (lid & 15);
                ldsm4(r4, smem_u32(&Khs[rB][ac]));
                bh[2*jp][0]=r4[0]; bh[2*jp][1]=r4[2]; bh[2*jp+1][0]=r4[1]; bh[2*jp+1][1]=r4[3];
                ldsm4(r4, smem_u32(&Kls[rB][ac]));
                bl[2*jp][0]=r4[0]; bl[2*jp][1]=r4[2]; bl[2*jp+1][0]=r4[1]; bl[2*jp+1][1]=r4[3];
            }
            #pragma unroll
            for (int j = 0; j < 8; j++) {
                mma16816(s[j], ahf, bh[j]);
                mma16816(s[j], ahf, bl[j]);
                mma16816(s[j], alf, bh[j]);
            }
        }

        float rm0 = -INFINITY, rm1 = -INFINITY;
        #pragma unroll
        for (int j = 0; j < 8; j++) {
            rm0 = fmaxf(rm0, fmaxf(s[j][0], s[j][1]));
            rm1 = fmaxf(rm1, fmaxf(s[j][2], s[j][3]));
        }
        rm0 = fmaxf(rm0, __shfl_xor_sync(~0u, rm0, 1)); rm0 = fmaxf(rm0, __shfl_xor_sync(~0u, rm0, 2));
        rm1 = fmaxf(rm1, __shfl_xor_sync(~0u, rm1, 1)); rm1 = fmaxf(rm1, __shfl_xor_sync(~0u, rm1, 2));
        float mn0 = fmaxf(m0r, rm0), mn1 = fmaxf(m1r, rm1);
        float c0 = ex2f(m0r - mn0), c1 = ex2f(m1r - mn1);
        m0r = mn0; m1r = mn1;
        float s0 = 0.f, s1 = 0.f;
        #pragma unroll
        for (int j = 0; j < 8; j++) {
            s[j][0] = ex2f(s[j][0] - mn0); s[j][1] = ex2f(s[j][1] - mn0);
            s[j][2] = ex2f(s[j][2] - mn1); s[j][3] = ex2f(s[j][3] - mn1);
            s0 += s[j][0] + s[j][1]; s1 += s[j][2] + s[j][3];
        }
        s0 += __shfl_xor_sync(~0u, s0, 1); s0 += __shfl_xor_sync(~0u, s0, 2);
        s1 += __shfl_xor_sync(~0u, s1, 1); s1 += __shfl_xor_sync(~0u, s1, 2);
        l0r = l0r * c0 + s0; l1r = l1r * c1 + s1;
        #pragma unroll
        for (int j = 0; j < 8; j++) { O[j][0] *= c0; O[j][1] *= c0; O[j][2] *= c1; O[j][3] *= c1; }

        uint32_t ph[4][4], pl[4][4];
        #pragma unroll
        for (int j2 = 0; j2 < 4; j2++) {
            int t0 = 2 * j2, t1 = t0 + 1;
            ph[j2][0] = pack_bf16(s[t0][0], s[t0][1]); ph[j2][1] = pack_bf16(s[t0][2], s[t0][3]);
            ph[j2][2] = pack_bf16(s[t1][0], s[t1][1]); ph[j2][3] = pack_bf16(s[t1][2], s[t1][3]);
            #pragma unroll
            for (int q = 0; q < 4; q++) {
                __nv_bfloat162 u = *(__nv_bfloat162*)&ph[j2][q];
                const float* sv = (q < 2) ? s[t0] : s[t1];
                int b = (q & 1) * 2;
                pl[j2][q] = pack_bf16(sv[b] - __bfloat162float(u.x),
                                      sv[b + 1] - __bfloat162float(u.y));
            }
        }

        #pragma unroll
        for (int j2 = 0; j2 < 4; j2++) {
            uint32_t vh[8][2], vl[8][2], r4[4];
            #pragma unroll
            for (int np = 0; np < 4; np++) {
                int rV = 16 * j2 + (lid & 15), cV = 16 * np + ((lid >> 4) << 3);
                ldsm4t(r4, smem_u32(&Vhs[rV][cV]));
                vh[2*np][0]=r4[0]; vh[2*np][1]=r4[1]; vh[2*np+1][0]=r4[2]; vh[2*np+1][1]=r4[3];
                ldsm4t(r4, smem_u32(&Vls[rV][cV]));
                vl[2*np][0]=r4[0]; vl[2*np][1]=r4[1]; vl[2*np+1][0]=r4[2]; vl[2*np+1][1]=r4[3];
            }
            #pragma unroll
            for (int tt = 0; tt < 8; tt++) {
                mma16816(O[tt], ph[j2], vh[tt]);
                mma16816(O[tt], ph[j2], vl[tt]);
                mma16816(O[tt], pl[j2], vh[tt]);
            }
        }
    }

    float i0 = 1.f / l0r, i1 = 1.f / l1r;
    #pragma unroll
    for (int t = 0; t < 8; t++) {
        int c = h * DK + 8 * t + (lid & 3) * 2;
        int r0 = q0 + 16 * w + (lid >> 2);
        #pragma unroll
        for (int hrow = 0; hrow < 2; hrow++) {
            float f0 = O[t][2*hrow]   * (hrow ? i1 : i0);
            float f1 = O[t][2*hrow+1] * (hrow ? i1 : i0);
            uint32_t hp = pack_bf16(f0, f1);
            __nv_bfloat162 u = *(__nv_bfloat162*)&hp;
            size_t dst = (size_t)(r0 + hrow * 8) * DMODEL + c;
            *(uint32_t*)(Ah + dst) = hp;
            *(uint32_t*)(Al + dst) = pack_bf16(f0 - __bfloat162float(u.x),
                                               f1 - __bfloat162float(u.y));
        }
    }
}

extern "C" void kernel_launch(void* const* d_in, const int* in_sizes, int n_in,
                              void* d_out, int out_size)
{
    const float* q  = (const float*)d_in[0];
    const float* k  = (const float*)d_in[1];
    const float* v  = (const float*)d_in[2];
    const float* Wq = (const float*)d_in[3];
    const float* bq = (const float*)d_in[4];
    const float* Wo = (const float*)d_in[5];
    const float* bo = (const float*)d_in[6];
    float* out = (float*)d_out;

    __nv_bfloat16 *xh, *xl, *wh, *wl, *qh, *ql, *kh, *kl, *vh, *vl, *ah, *al;
    cudaGetSymbolAddress((void**)&xh, g_xh); cudaGetSymbolAddress((void**)&xl, g_xl);
    cudaGetSymbolAddress((void**)&wh, g_wh); cudaGetSymbolAddress((void**)&wl, g_wl);
    cudaGetSymbolAddress((void**)&qh, g_qh); cudaGetSymbolAddress((void**)&ql, g_ql);
    cudaGetSymbolAddress((void**)&kh, g_kh); cudaGetSymbolAddress((void**)&kl, g_kl);
    cudaGetSymbolAddress((void**)&vh, g_vh); cudaGetSymbolAddress((void**)&vl, g_vl);
    cudaGetSymbolAddress((void**)&ah, g_ah); cudaGetSymbolAddress((void**)&al, g_al);

    cudaFuncSetAttribute(attn_tc,  cudaFuncAttributeMaxDynamicSharedMemorySize, AT_SMEM);
    cudaFuncSetAttribute(qkv_proj, cudaFuncAttributeMaxDynamicSharedMemorySize, PROJ_SMEM);
    cudaFuncSetAttribute(out_proj, cudaFuncAttributeMaxDynamicSharedMemorySize, PROJ_SMEM);

    conv_hilo<<<XN / 4 / 256, 256>>>(q, xh,          xl,          XN / 4);
    conv_hilo<<<XN / 4 / 256, 256>>>(k, xh + XN,     xl + XN,     XN / 4);
    conv_hilo<<<XN / 4 / 256, 256>>>(v, xh + 2 * XN, xl + 2 * XN, XN / 4);
    conv_hilo<<<WN / 4 / 256, 256>>>(Wq, wh,      wl,      WN / 4);
    conv_hilo<<<WN / 4 / 256, 256>>>(Wo, wh + WN, wl + WN, WN / 4);

    dim3 gqkv(DMODEL / 128, S_LEN / 128, 3);   // 6 x 32 x 3
    qkv_proj<<<gqkv, 256, PROJ_SMEM>>>(xh, xl, wh, wl, bq, qh, ql, kh, kl, vh, vl);

    dim3 gattn(S_LEN / 128, NH);               // 32 x 12
    attn_tc<<<gattn, 256, AT_SMEM>>>(qh, ql, kh, kl, vh, vl, ah, al);

    dim3 gout(DMODEL / 128, S_LEN / 128);      // 6 x 32
    out_proj<<<gout, 256, PROJ_SMEM>>>(ah, al, wh + WN, wl + WN, bo, out);
}